// round 2
// baseline (speedup 1.0000x reference)
#include <cuda_runtime.h>
#include <cuda_bf16.h>
#include <cstdint>

using bf16 = __nv_bfloat16;

// Problem dims
static constexpr int NB = 8, NS = 1024, ND = 512, NK = 64, NH = 8;

static constexpr size_t SZ_X  = (size_t)NB * NS * ND;          // 4,194,304
static constexpr size_t SZ_VT = (size_t)NB * (ND * NH) * NS;   // 33,554,432
static constexpr size_t SZ_SC = (size_t)NH * NB * NS * NS;     // 67,108,864
static constexpr size_t SZ_O  = (size_t)NB * NS * (NH * ND);   // 33,554,432

// -------- static scratch (no runtime allocation allowed) --------
__device__ bf16  g_xb [SZ_X];
__device__ bf16  g_qb [SZ_X];
__device__ bf16  g_kb [SZ_X];
__device__ bf16  g_wqt[ND * (NK * NH)];   // [512][512]  WqT
__device__ bf16  g_wkt[ND * (NK * NH)];   // [512][512]  WkT
__device__ bf16  g_wvt[(ND * NH) * ND];   // [4096][512] WvT
__device__ bf16  g_wot[ND * (ND * NH)];   // [512][4096] WoT
__device__ bf16  g_vt [SZ_VT];            // [b][4096][1024]  V^T per batch
__device__ float g_sc [SZ_SC];            // [h][b][1024][1024] scores (scaled)
__device__ bf16  g_att[SZ_SC];            // softmax(att), bf16
__device__ bf16  g_ob [SZ_O];             // [8192][4096] attention output
__device__ float g_y  [SZ_X];             // pre-LN (o@Wo + bo + x)

// ---------------------------------------------------------------
__device__ __forceinline__ uint32_t pack_bf16(float lo, float hi) {
    return ((uint32_t)__bfloat16_as_ushort(__float2bfloat16(hi)) << 16) |
            (uint32_t)__bfloat16_as_ushort(__float2bfloat16(lo));
}

__device__ __forceinline__ void mma16816(float* d, const uint32_t* a, const uint32_t* b) {
    asm volatile(
        "mma.sync.aligned.m16n8k16.row.col.f32.bf16.bf16.f32 "
        "{%0,%1,%2,%3}, {%4,%5,%6,%7}, {%8,%9}, {%0,%1,%2,%3};\n"
        : "+f"(d[0]), "+f"(d[1]), "+f"(d[2]), "+f"(d[3])
        : "r"(a[0]), "r"(a[1]), "r"(a[2]), "r"(a[3]), "r"(b[0]), "r"(b[1]));
}

// -------- elementwise convert fp32 -> bf16 --------
__global__ void f32_to_bf16_k(const float* __restrict__ in, bf16* __restrict__ out, int n) {
    int i = (blockIdx.x * blockDim.x + threadIdx.x) * 4;
    if (i >= n) return;
    float4 v = *reinterpret_cast<const float4*>(in + i);
    uint2 u;
    u.x = pack_bf16(v.x, v.y);
    u.y = pack_bf16(v.z, v.w);
    *reinterpret_cast<uint2*>(out + i) = u;
}

// -------- transpose + convert: out[c][r] = in[r][c]  (R, C multiples of 32) --------
__global__ void transpose_to_bf16(const float* __restrict__ in, bf16* __restrict__ out,
                                  int R, int C) {
    __shared__ float t[32][33];
    int c0 = blockIdx.x * 32, r0 = blockIdx.y * 32;
    int tx = threadIdx.x;
    for (int i = threadIdx.y; i < 32; i += 8)
        t[i][tx] = in[(size_t)(r0 + i) * C + c0 + tx];
    __syncthreads();
    for (int i = threadIdx.y; i < 32; i += 8)
        out[(size_t)(c0 + i) * R + r0 + tx] = __float2bfloat16(t[tx][i]);
}

// -------- generic batched bf16 GEMM: C[m,n] = alpha * sum_k A[m,k] * B[n,k] --------
// MODE 0: fp32 store     MODE 1: bf16 store     MODE 2: fp32 store + bias[n] + resid[m,n]
// z = blockIdx.z; z1 = z % Z1, z2 = z / Z1; per-operand offsets z1*s?1 + z2*s?2 (elements).
#define BM 128
#define BN 128
#define BK 32
#define BKP 40   // padded smem row (bf16 elems) -> 20 uint32, conflict-free fragment LDS

template <int MODE>
__global__ __launch_bounds__(256, 2)
void gemm_bf16_tn(const bf16* __restrict__ A, const bf16* __restrict__ B,
                  void* __restrict__ Cv,
                  int M, int N, int Kd, int lda, int ldb, int ldc,
                  long long sA1, long long sA2, long long sB1, long long sB2,
                  long long sC1, long long sC2, int Z1,
                  float alpha, const float* __restrict__ bias,
                  const float* __restrict__ resid, int ldres) {
    int z = blockIdx.z;
    int z1 = z % Z1, z2 = z / Z1;
    A += (size_t)z1 * sA1 + (size_t)z2 * sA2;
    B += (size_t)z1 * sB1 + (size_t)z2 * sB2;
    long long coff = (long long)z1 * sC1 + (long long)z2 * sC2;

    __shared__ alignas(16) bf16 As[BM][BKP];
    __shared__ alignas(16) bf16 Bs[BN][BKP];

    int tid  = threadIdx.x;
    int warp = tid >> 5, lane = tid & 31;
    int wm = (warp & 1) * 64;   // warp M offset (2 warps over M)
    int wn = (warp >> 1) * 32;  // warp N offset (4 warps over N)
    int bm0 = blockIdx.y * BM;
    int bn0 = blockIdx.x * BN;

    float acc[4][4][4];
#pragma unroll
    for (int i = 0; i < 4; i++)
#pragma unroll
        for (int j = 0; j < 4; j++)
#pragma unroll
            for (int r = 0; r < 4; r++) acc[i][j][r] = 0.f;

    int lr = tid >> 2;         // 0..63
    int lc = (tid & 3) * 8;    // 0,8,16,24

    int rq = lane >> 2;        // 0..7
    int cq = lane & 3;         // 0..3

    for (int kt = 0; kt < Kd; kt += BK) {
#pragma unroll
        for (int i = 0; i < 2; i++) {
            int r = lr + i * 64;
            uint4 va = *reinterpret_cast<const uint4*>(A + (size_t)(bm0 + r) * lda + kt + lc);
            *reinterpret_cast<uint4*>(&As[r][lc]) = va;
            uint4 vb = *reinterpret_cast<const uint4*>(B + (size_t)(bn0 + r) * ldb + kt + lc);
            *reinterpret_cast<uint4*>(&Bs[r][lc]) = vb;
        }
        __syncthreads();

        const uint32_t* UA = reinterpret_cast<const uint32_t*>(&As[0][0]);
        const uint32_t* UB = reinterpret_cast<const uint32_t*>(&Bs[0][0]);
#pragma unroll
        for (int ks = 0; ks < 2; ks++) {
            int kk = ks * 8;  // uint32 offset = 16 bf16
            uint32_t afr[4][4];
#pragma unroll
            for (int i = 0; i < 4; i++) {
                int r0 = wm + i * 16 + rq;
                afr[i][0] = UA[r0 * 20 + kk + cq];
                afr[i][1] = UA[(r0 + 8) * 20 + kk + cq];
                afr[i][2] = UA[r0 * 20 + kk + 4 + cq];
                afr[i][3] = UA[(r0 + 8) * 20 + kk + 4 + cq];
            }
            uint32_t bfr[4][2];
#pragma unroll
            for (int j = 0; j < 4; j++) {
                int n0 = wn + j * 8 + rq;
                bfr[j][0] = UB[n0 * 20 + kk + cq];
                bfr[j][1] = UB[n0 * 20 + kk + 4 + cq];
            }
#pragma unroll
            for (int i = 0; i < 4; i++)
#pragma unroll
                for (int j = 0; j < 4; j++)
                    mma16816(acc[i][j], afr[i], bfr[j]);
        }
        __syncthreads();
    }

    // -------- epilogue --------
    int cq2 = cq * 2;
    float* Cf = (MODE == 1) ? nullptr : (float*)Cv + coff;
    bf16*  Cb = (MODE == 1) ? (bf16*)Cv + coff : nullptr;
#pragma unroll
    for (int i = 0; i < 4; i++) {
#pragma unroll
        for (int j = 0; j < 4; j++) {
            int row = bm0 + wm + i * 16 + rq;
            int col = bn0 + wn + j * 8 + cq2;
            float c0 = acc[i][j][0] * alpha, c1 = acc[i][j][1] * alpha;
            float c2 = acc[i][j][2] * alpha, c3 = acc[i][j][3] * alpha;
            if (MODE == 2) {
                float b0v = bias[col], b1v = bias[col + 1];
                const float* r0p = resid + (size_t)row * ldres + col;
                const float* r1p = resid + (size_t)(row + 8) * ldres + col;
                c0 += b0v + r0p[0]; c1 += b1v + r0p[1];
                c2 += b0v + r1p[0]; c3 += b1v + r1p[1];
            }
            if (MODE == 1) {
                *reinterpret_cast<uint32_t*>(Cb + (size_t)row * ldc + col)       = pack_bf16(c0, c1);
                *reinterpret_cast<uint32_t*>(Cb + (size_t)(row + 8) * ldc + col) = pack_bf16(c2, c3);
            } else {
                *reinterpret_cast<float2*>(Cf + (size_t)row * ldc + col)       = make_float2(c0, c1);
                *reinterpret_cast<float2*>(Cf + (size_t)(row + 8) * ldc + col) = make_float2(c2, c3);
            }
        }
    }
}

// -------- softmax over last dim (1024) with exact-zero mask, writes bf16 --------
__global__ void softmax_mask_k(const float* __restrict__ sc, bf16* __restrict__ att) {
    const long long row = blockIdx.x;
    const float* p = sc + row * 1024;
    bf16* o = att + row * 1024;
    int t = threadIdx.x;  // 256 threads
    float2 v0 = *reinterpret_cast<const float2*>(p + 2 * t);
    float2 v1 = *reinterpret_cast<const float2*>(p + 512 + 2 * t);
    if (v0.x == 0.f) v0.x = -1e9f;
    if (v0.y == 0.f) v0.y = -1e9f;
    if (v1.x == 0.f) v1.x = -1e9f;
    if (v1.y == 0.f) v1.y = -1e9f;
    float mx = fmaxf(fmaxf(v0.x, v0.y), fmaxf(v1.x, v1.y));
#pragma unroll
    for (int o2 = 16; o2; o2 >>= 1) mx = fmaxf(mx, __shfl_xor_sync(0xffffffffu, mx, o2));
    __shared__ float sm[8];
    if ((t & 31) == 0) sm[t >> 5] = mx;
    __syncthreads();
    mx = sm[0];
#pragma unroll
    for (int i = 1; i < 8; i++) mx = fmaxf(mx, sm[i]);

    float e0 = __expf(v0.x - mx), e1 = __expf(v0.y - mx);
    float e2 = __expf(v1.x - mx), e3 = __expf(v1.y - mx);
    float s = e0 + e1 + e2 + e3;
#pragma unroll
    for (int o2 = 16; o2; o2 >>= 1) s += __shfl_xor_sync(0xffffffffu, s, o2);
    __shared__ float ss[8];
    if ((t & 31) == 0) ss[t >> 5] = s;
    __syncthreads();
    s = ss[0] + ss[1] + ss[2] + ss[3] + ss[4] + ss[5] + ss[6] + ss[7];
    float inv = 1.0f / s;
    *reinterpret_cast<uint32_t*>(o + 2 * t)       = pack_bf16(e0 * inv, e1 * inv);
    *reinterpret_cast<uint32_t*>(o + 512 + 2 * t) = pack_bf16(e2 * inv, e3 * inv);
}

// -------- LayerNorm over D=512, eps=1e-6, writes final output --------
__global__ void layernorm_k(const float* __restrict__ y, const float* __restrict__ gamma,
                            const float* __restrict__ beta, float* __restrict__ out) {
    int row = blockIdx.x;
    int t = threadIdx.x;  // 128 threads, 4 floats each
    const float4* p = reinterpret_cast<const float4*>(y + (size_t)row * 512);
    float4 v = p[t];
    float s = v.x + v.y + v.z + v.w;
#pragma unroll
    for (int o = 16; o; o >>= 1) s += __shfl_xor_sync(0xffffffffu, s, o);
    __shared__ float sm[4];
    if ((t & 31) == 0) sm[t >> 5] = s;
    __syncthreads();
    float mu = (sm[0] + sm[1] + sm[2] + sm[3]) * (1.0f / 512.0f);
    float dx = v.x - mu, dy = v.y - mu, dz = v.z - mu, dw = v.w - mu;
    float q = dx * dx + dy * dy + dz * dz + dw * dw;
#pragma unroll
    for (int o = 16; o; o >>= 1) q += __shfl_xor_sync(0xffffffffu, q, o);
    __shared__ float sq[4];
    if ((t & 31) == 0) sq[t >> 5] = q;
    __syncthreads();
    float var = (sq[0] + sq[1] + sq[2] + sq[3]) * (1.0f / 512.0f);
    float rs = rsqrtf(var + 1e-6f);
    float4 g = reinterpret_cast<const float4*>(gamma)[t];
    float4 b = reinterpret_cast<const float4*>(beta)[t];
    float4 r;
    r.x = dx * rs * g.x + b.x;
    r.y = dy * rs * g.y + b.y;
    r.z = dz * rs * g.z + b.z;
    r.w = dw * rs * g.w + b.w;
    reinterpret_cast<float4*>(out + (size_t)row * 512)[t] = r;
}

// ---------------------------------------------------------------
extern "C" void kernel_launch(void* const* d_in, const int* in_sizes, int n_in,
                              void* d_out, int out_size) {
    const float* x     = (const float*)d_in[0];
    const float* Wq    = (const float*)d_in[1];
    const float* Wk    = (const float*)d_in[2];
    const float* Wv    = (const float*)d_in[3];
    const float* Wo    = (const float*)d_in[4];
    const float* bo    = (const float*)d_in[5];
    const float* gamma = (const float*)d_in[6];
    const float* beta  = (const float*)d_in[7];
    float* out = (float*)d_out;

    bf16 *xb, *qb, *kb, *wqt, *wkt, *wvt, *wot, *vt, *att, *ob;
    float *sc, *yb;
    cudaGetSymbolAddress((void**)&xb,  g_xb);
    cudaGetSymbolAddress((void**)&qb,  g_qb);
    cudaGetSymbolAddress((void**)&kb,  g_kb);
    cudaGetSymbolAddress((void**)&wqt, g_wqt);
    cudaGetSymbolAddress((void**)&wkt, g_wkt);
    cudaGetSymbolAddress((void**)&wvt, g_wvt);
    cudaGetSymbolAddress((void**)&wot, g_wot);
    cudaGetSymbolAddress((void**)&vt,  g_vt);
    cudaGetSymbolAddress((void**)&sc,  g_sc);
    cudaGetSymbolAddress((void**)&att, g_att);
    cudaGetSymbolAddress((void**)&ob,  g_ob);
    cudaGetSymbolAddress((void**)&yb,  g_y);

    // 1) x -> bf16
    f32_to_bf16_k<<<(int)(SZ_X / 4 / 256), 256>>>(x, xb, (int)SZ_X);
    // 2) transposed bf16 weights
    transpose_to_bf16<<<dim3(16, 16),  dim3(32, 8)>>>(Wq, wqt, 512, 512);
    transpose_to_bf16<<<dim3(16, 16),  dim3(32, 8)>>>(Wk, wkt, 512, 512);
    transpose_to_bf16<<<dim3(128, 16), dim3(32, 8)>>>(Wv, wvt, 512, 4096);
    transpose_to_bf16<<<dim3(16, 128), dim3(32, 8)>>>(Wo, wot, 4096, 512);

    // 3) q = x @ Wq   [8192,512]
    gemm_bf16_tn<1><<<dim3(4, 64, 1), 256>>>(xb, wqt, qb, 8192, 512, 512,
        512, 512, 512, 0, 0, 0, 0, 0, 0, 1, 1.0f, nullptr, nullptr, 0);
    // 4) k = x @ Wk
    gemm_bf16_tn<1><<<dim3(4, 64, 1), 256>>>(xb, wkt, kb, 8192, 512, 512,
        512, 512, 512, 0, 0, 0, 0, 0, 0, 1, 1.0f, nullptr, nullptr, 0);
    // 5) Vt[b] = WvT @ x[b]^T  -> [b][4096][1024]
    gemm_bf16_tn<1><<<dim3(8, 32, 8), 256>>>(wvt, xb, vt, 4096, 1024, 512,
        512, 512, 1024, 0, 0, 0, 524288LL, 0, 4194304LL, 1, 1.0f, nullptr, nullptr, 0);
    // 6) scores[h][b] = (Q_hb @ K_hb^T) / sqrt(64)
    gemm_bf16_tn<0><<<dim3(8, 8, 64), 256>>>(qb, kb, sc, 1024, 1024, 64,
        512, 512, 1024, 64LL, 524288LL, 64LL, 524288LL, 8388608LL, 1048576LL, 8,
        0.125f, nullptr, nullptr, 0);
    // 7) softmax with zero-mask -> att (bf16)
    softmax_mask_k<<<65536, 256>>>(sc, att);
    // 8) o[b,q,h,:] = att_hb @ V_hb    -> [8192][4096]
    gemm_bf16_tn<1><<<dim3(4, 8, 64), 256>>>(att, vt, ob, 1024, 512, 1024,
        1024, 1024, 4096, 8388608LL, 1048576LL, 524288LL, 4194304LL, 512LL, 4194304LL, 8,
        1.0f, nullptr, nullptr, 0);
    // 9) y = o @ Wo + bo + x
    gemm_bf16_tn<2><<<dim3(4, 64, 1), 256>>>(ob, wot, yb, 8192, 512, 4096,
        4096, 4096, 512, 0, 0, 0, 0, 0, 0, 1, 1.0f, bo, x, 512);
    // 10) LayerNorm -> out
    layernorm_k<<<8192, 128>>>(yb, gamma, beta, out);
}

// round 3
// speedup vs baseline: 1.0369x; 1.0369x over previous
#include <cuda_runtime.h>
#include <cuda_bf16.h>
#include <cstdint>

using bf16 = __nv_bfloat16;

// Problem dims
static constexpr int NB = 8, NS = 1024, ND = 512, NK = 64, NH = 8;

static constexpr size_t SZ_X  = (size_t)NB * NS * ND;          // 4,194,304
static constexpr size_t SZ_VT = (size_t)NB * (ND * NH) * NS;   // 33,554,432
static constexpr size_t SZ_O  = (size_t)NB * NS * (NH * ND);   // 33,554,432

// -------- static scratch (no runtime allocation allowed) --------
__device__ bf16  g_xb [SZ_X];
__device__ bf16  g_qb [SZ_X];
__device__ bf16  g_kb [SZ_X];
__device__ bf16  g_wqt[ND * (NK * NH)];   // [512][512]  WqT
__device__ bf16  g_wkt[ND * (NK * NH)];   // [512][512]  WkT
__device__ bf16  g_wvt[(ND * NH) * ND];   // [4096][512] WvT
__device__ bf16  g_wot[ND * (ND * NH)];   // [512][4096] WoT
__device__ bf16  g_vt [SZ_VT];            // [b][4096][1024]  V^T per batch
__device__ bf16  g_ob [SZ_O];             // [8192][4096] attention output
__device__ float g_y  [SZ_X];             // pre-LN (o@Wo + bo + x)

// ---------------------------------------------------------------
__device__ __forceinline__ uint32_t pack_bf16(float lo, float hi) {
    return ((uint32_t)__bfloat16_as_ushort(__float2bfloat16(hi)) << 16) |
            (uint32_t)__bfloat16_as_ushort(__float2bfloat16(lo));
}

__device__ __forceinline__ void mma16816(float* d, const uint32_t* a, const uint32_t* b) {
    asm volatile(
        "mma.sync.aligned.m16n8k16.row.col.f32.bf16.bf16.f32 "
        "{%0,%1,%2,%3}, {%4,%5,%6,%7}, {%8,%9}, {%0,%1,%2,%3};\n"
        : "+f"(d[0]), "+f"(d[1]), "+f"(d[2]), "+f"(d[3])
        : "r"(a[0]), "r"(a[1]), "r"(a[2]), "r"(a[3]), "r"(b[0]), "r"(b[1]));
}

__device__ __forceinline__ void cpasync16(void* s, const void* g) {
    uint32_t sa = (uint32_t)__cvta_generic_to_shared(s);
    asm volatile("cp.async.cg.shared.global [%0], [%1], 16;\n" :: "r"(sa), "l"(g));
}
__device__ __forceinline__ void cpcommit() { asm volatile("cp.async.commit_group;\n" ::: "memory"); }
__device__ __forceinline__ void cpwait0()  { asm volatile("cp.async.wait_group 0;\n" ::: "memory"); }

// -------- elementwise convert fp32 -> bf16 --------
__global__ void f32_to_bf16_k(const float* __restrict__ in, bf16* __restrict__ out, int n) {
    int i = (blockIdx.x * blockDim.x + threadIdx.x) * 4;
    if (i >= n) return;
    float4 v = *reinterpret_cast<const float4*>(in + i);
    uint2 u;
    u.x = pack_bf16(v.x, v.y);
    u.y = pack_bf16(v.z, v.w);
    *reinterpret_cast<uint2*>(out + i) = u;
}

// -------- transpose + convert: out[c][r] = in[r][c] --------
__global__ void transpose_to_bf16(const float* __restrict__ in, bf16* __restrict__ out,
                                  int R, int C) {
    __shared__ float t[32][33];
    int c0 = blockIdx.x * 32, r0 = blockIdx.y * 32;
    int tx = threadIdx.x;
    for (int i = threadIdx.y; i < 32; i += 8)
        t[i][tx] = in[(size_t)(r0 + i) * C + c0 + tx];
    __syncthreads();
    for (int i = threadIdx.y; i < 32; i += 8)
        out[(size_t)(c0 + i) * R + r0 + tx] = __float2bfloat16(t[tx][i]);
}

// -------- generic batched bf16 GEMM (cp.async double-buffered) --------
// C[m,n] = alpha * sum_k A[m,k] * B[n,k]
// MODE 1: bf16 store     MODE 2: fp32 store + bias[n] + resid[m,n]
#define BM 128
#define BN 128
#define BK 32
#define BKP 40   // padded smem row (bf16) -> 20 uint32, stride%32==20 conflict-free

template <int MODE>
__global__ __launch_bounds__(256, 2)
void gemm_bf16_tn(const bf16* __restrict__ A, const bf16* __restrict__ B,
                  void* __restrict__ Cv,
                  int M, int N, int Kd, int lda, int ldb, int ldc,
                  long long sA1, long long sA2, long long sB1, long long sB2,
                  long long sC1, long long sC2, int Z1,
                  float alpha, const float* __restrict__ bias,
                  const float* __restrict__ resid, int ldres) {
    int z = blockIdx.z;
    int z1 = z % Z1, z2 = z / Z1;
    A += (size_t)z1 * sA1 + (size_t)z2 * sA2;
    B += (size_t)z1 * sB1 + (size_t)z2 * sB2;
    long long coff = (long long)z1 * sC1 + (long long)z2 * sC2;

    __shared__ alignas(16) bf16 As[2][BM][BKP];
    __shared__ alignas(16) bf16 Bs[2][BN][BKP];

    int tid  = threadIdx.x;
    int warp = tid >> 5, lane = tid & 31;
    int wm = (warp & 1) * 64;
    int wn = (warp >> 1) * 32;
    int bm0 = blockIdx.y * BM;
    int bn0 = blockIdx.x * BN;

    float acc[4][4][4];
#pragma unroll
    for (int i = 0; i < 4; i++)
#pragma unroll
        for (int j = 0; j < 4; j++)
#pragma unroll
            for (int r = 0; r < 4; r++) acc[i][j][r] = 0.f;

    int lr = tid >> 2;
    int lc = (tid & 3) * 8;
    int rq = lane >> 2;
    int cq = lane & 3;

    // prologue: stage 0
#pragma unroll
    for (int i = 0; i < 2; i++) {
        int r = lr + i * 64;
        cpasync16(&As[0][r][lc], A + (size_t)(bm0 + r) * lda + lc);
        cpasync16(&Bs[0][r][lc], B + (size_t)(bn0 + r) * ldb + lc);
    }
    cpcommit();

    int p = 0;
    for (int kt = 0; kt < Kd; kt += BK, p ^= 1) {
        cpwait0();
        __syncthreads();
        if (kt + BK < Kd) {
            int np = p ^ 1;
#pragma unroll
            for (int i = 0; i < 2; i++) {
                int r = lr + i * 64;
                cpasync16(&As[np][r][lc], A + (size_t)(bm0 + r) * lda + kt + BK + lc);
                cpasync16(&Bs[np][r][lc], B + (size_t)(bn0 + r) * ldb + kt + BK + lc);
            }
            cpcommit();
        }

        const uint32_t* UA = reinterpret_cast<const uint32_t*>(&As[p][0][0]);
        const uint32_t* UB = reinterpret_cast<const uint32_t*>(&Bs[p][0][0]);
#pragma unroll
        for (int ks = 0; ks < 2; ks++) {
            int kk = ks * 8;
            uint32_t afr[4][4];
#pragma unroll
            for (int i = 0; i < 4; i++) {
                int r0 = wm + i * 16 + rq;
                afr[i][0] = UA[r0 * 20 + kk + cq];
                afr[i][1] = UA[(r0 + 8) * 20 + kk + cq];
                afr[i][2] = UA[r0 * 20 + kk + 4 + cq];
                afr[i][3] = UA[(r0 + 8) * 20 + kk + 4 + cq];
            }
            uint32_t bfr[4][2];
#pragma unroll
            for (int j = 0; j < 4; j++) {
                int n0 = wn + j * 8 + rq;
                bfr[j][0] = UB[n0 * 20 + kk + cq];
                bfr[j][1] = UB[n0 * 20 + kk + 4 + cq];
            }
#pragma unroll
            for (int i = 0; i < 4; i++)
#pragma unroll
                for (int j = 0; j < 4; j++)
                    mma16816(acc[i][j], afr[i], bfr[j]);
        }
        __syncthreads();
    }

    // -------- epilogue --------
    int cq2 = cq * 2;
    float* Cf = (MODE == 1) ? nullptr : (float*)Cv + coff;
    bf16*  Cb = (MODE == 1) ? (bf16*)Cv + coff : nullptr;
#pragma unroll
    for (int i = 0; i < 4; i++) {
#pragma unroll
        for (int j = 0; j < 4; j++) {
            int row = bm0 + wm + i * 16 + rq;
            int col = bn0 + wn + j * 8 + cq2;
            float c0 = acc[i][j][0] * alpha, c1 = acc[i][j][1] * alpha;
            float c2 = acc[i][j][2] * alpha, c3 = acc[i][j][3] * alpha;
            if (MODE == 2) {
                float b0v = bias[col], b1v = bias[col + 1];
                const float* r0p = resid + (size_t)row * ldres + col;
                const float* r1p = resid + (size_t)(row + 8) * ldres + col;
                c0 += b0v + r0p[0]; c1 += b1v + r0p[1];
                c2 += b0v + r1p[0]; c3 += b1v + r1p[1];
            }
            if (MODE == 1) {
                *reinterpret_cast<uint32_t*>(Cb + (size_t)row * ldc + col)       = pack_bf16(c0, c1);
                *reinterpret_cast<uint32_t*>(Cb + (size_t)(row + 8) * ldc + col) = pack_bf16(c2, c3);
            } else {
                *reinterpret_cast<float2*>(Cf + (size_t)row * ldc + col)       = make_float2(c0, c1);
                *reinterpret_cast<float2*>(Cf + (size_t)(row + 8) * ldc + col) = make_float2(c2, c3);
            }
        }
    }
}

// ================================================================
// Fused flash attention: scores (QK^T/8) + zero-mask + online softmax + P·V
// Block: q-tile 128 x d-chunk 128 for one (b,h). 8 s-iterations of 128.
// grid = (32, 64): x = dch*8 + qt, y = b*8 + h.
// Smem (bf16 elems): Q[128*72] | K[2][128*72] | V[2][128*136] | P[128*136] | red
// All fragment strides % 32 == 4 (in u32) -> conflict-free.
// ================================================================
static constexpr int FQS = 72;    // Q/K row stride bf16 (36 u32)
static constexpr int FVS = 136;   // V/P row stride bf16 (68 u32)
static constexpr int FLASH_SMEM = (128*FQS + 2*128*FQS + 2*128*FVS + 128*FVS) * 2 + 2 * 512 * 4;

__global__ __launch_bounds__(256)
void flash_attn_k(const bf16* __restrict__ Qg, const bf16* __restrict__ Kg,
                  const bf16* __restrict__ Vg, bf16* __restrict__ Og) {
    extern __shared__ __align__(16) char fsm[];
    bf16*  Qs  = (bf16*)fsm;             // 128*72
    bf16*  Ks  = Qs + 128 * FQS;         // 2 bufs of 128*72
    bf16*  Vs  = Ks + 2 * 128 * FQS;     // 2 bufs of 128*136
    bf16*  Ps  = Vs + 2 * 128 * FVS;     // 128*136
    float* redm = (float*)(Ps + 128 * FVS);  // [4][128]
    float* reds = redm + 512;                // [4][128]

    int tid  = threadIdx.x;
    int warp = tid >> 5, lane = tid & 31;
    int wm = (warp & 1) * 64, wn = (warp >> 1) * 32, g = warp >> 1;
    int rq = lane >> 2, cq = lane & 3, cq2 = cq << 1;
    int qt = blockIdx.x & 7, dch = blockIdx.x >> 3;
    int b  = blockIdx.y >> 3, h = blockIdx.y & 7;

    const bf16* Qp = Qg + ((size_t)(b * 1024 + qt * 128)) * 512 + h * 64;
    const bf16* Kp = Kg + ((size_t)(b * 1024)) * 512 + h * 64;
    const bf16* Vp = Vg + (size_t)b * 4194304 + ((size_t)(h * 512 + dch * 128)) * 1024;

    // Q tile (resident) + K/V tile 0 into buffer 0, one commit group
#pragma unroll
    for (int p = 0; p < 4; p++) {
        int idx = tid + p * 256; int r = idx >> 3, c = (idx & 7) * 8;
        cpasync16(Qs + r * FQS + c, Qp + (size_t)r * 512 + c);
    }
#pragma unroll
    for (int p = 0; p < 4; p++) {
        int idx = tid + p * 256; int r = idx >> 3, c = (idx & 7) * 8;
        cpasync16(Ks + r * FQS + c, Kp + (size_t)r * 512 + c);
    }
#pragma unroll
    for (int p = 0; p < 8; p++) {
        int idx = tid + p * 256; int r = idx >> 4, c = (idx & 15) * 8;
        cpasync16(Vs + r * FVS + c, Vp + (size_t)r * 1024 + c);
    }
    cpcommit();

    float oacc[4][4][4];
#pragma unroll
    for (int i = 0; i < 4; i++)
#pragma unroll
        for (int j = 0; j < 4; j++)
#pragma unroll
            for (int r = 0; r < 4; r++) oacc[i][j][r] = 0.f;
    float m_st[4][2], l_st[4][2];
#pragma unroll
    for (int i = 0; i < 4; i++) { m_st[i][0] = -1e30f; m_st[i][1] = -1e30f; l_st[i][0] = 0.f; l_st[i][1] = 0.f; }

    int cur = 0;
    for (int st = 0; st < 8; st++) {
        cpwait0();
        __syncthreads();
        if (st < 7) {
            int nb = cur ^ 1;
            int s1 = (st + 1) * 128;
#pragma unroll
            for (int p = 0; p < 4; p++) {
                int idx = tid + p * 256; int r = idx >> 3, c = (idx & 7) * 8;
                cpasync16(Ks + nb * 128 * FQS + r * FQS + c, Kp + (size_t)(s1 + r) * 512 + c);
            }
#pragma unroll
            for (int p = 0; p < 8; p++) {
                int idx = tid + p * 256; int r = idx >> 4, c = (idx & 15) * 8;
                cpasync16(Vs + nb * 128 * FVS + r * FVS + c, Vp + (size_t)r * 1024 + s1 + c);
            }
            cpcommit();
        }

        // ---- S = Q·K^T (M=128 q, N=128 s, K=64) ----
        float sacc[4][4][4];
#pragma unroll
        for (int i = 0; i < 4; i++)
#pragma unroll
            for (int j = 0; j < 4; j++)
#pragma unroll
                for (int r = 0; r < 4; r++) sacc[i][j][r] = 0.f;

        const uint32_t* UQ = (const uint32_t*)Qs;
        const uint32_t* UK = (const uint32_t*)(Ks + cur * 128 * FQS);
#pragma unroll
        for (int ks = 0; ks < 4; ks++) {
            int kk = ks * 8;
            uint32_t afr[4][4];
#pragma unroll
            for (int i = 0; i < 4; i++) {
                int r0 = wm + i * 16 + rq;
                afr[i][0] = UQ[r0 * 36 + kk + cq];
                afr[i][1] = UQ[(r0 + 8) * 36 + kk + cq];
                afr[i][2] = UQ[r0 * 36 + kk + 4 + cq];
                afr[i][3] = UQ[(r0 + 8) * 36 + kk + 4 + cq];
            }
            uint32_t bfr[4][2];
#pragma unroll
            for (int j = 0; j < 4; j++) {
                int n0 = wn + j * 8 + rq;
                bfr[j][0] = UK[n0 * 36 + kk + cq];
                bfr[j][1] = UK[n0 * 36 + kk + 4 + cq];
            }
#pragma unroll
            for (int i = 0; i < 4; i++)
#pragma unroll
                for (int j = 0; j < 4; j++)
                    mma16816(sacc[i][j], afr[i], bfr[j]);
        }

        // scale 1/sqrt(64), exact-zero mask (raw==0 <=> scaled==0)
#pragma unroll
        for (int i = 0; i < 4; i++)
#pragma unroll
            for (int j = 0; j < 4; j++)
#pragma unroll
                for (int r = 0; r < 4; r++) {
                    float v = sacc[i][j][r];
                    sacc[i][j][r] = (v == 0.f) ? -1e9f : v * 0.125f;
                }

        // ---- rowmax (warp slice -> smem -> global) ----
#pragma unroll
        for (int i = 0; i < 4; i++) {
            float lo = -1e30f, hi = -1e30f;
#pragma unroll
            for (int j = 0; j < 4; j++) {
                lo = fmaxf(lo, fmaxf(sacc[i][j][0], sacc[i][j][1]));
                hi = fmaxf(hi, fmaxf(sacc[i][j][2], sacc[i][j][3]));
            }
            lo = fmaxf(lo, __shfl_xor_sync(0xffffffffu, lo, 1));
            lo = fmaxf(lo, __shfl_xor_sync(0xffffffffu, lo, 2));
            hi = fmaxf(hi, __shfl_xor_sync(0xffffffffu, hi, 1));
            hi = fmaxf(hi, __shfl_xor_sync(0xffffffffu, hi, 2));
            if (cq == 0) {
                redm[g * 128 + wm + i * 16 + rq]     = lo;
                redm[g * 128 + wm + i * 16 + rq + 8] = hi;
            }
        }
        __syncthreads();

        float scf[4][2];
#pragma unroll
        for (int i = 0; i < 4; i++)
#pragma unroll
            for (int hf = 0; hf < 2; hf++) {
                int r = wm + i * 16 + rq + hf * 8;
                float tm = fmaxf(fmaxf(redm[r], redm[128 + r]), fmaxf(redm[256 + r], redm[384 + r]));
                float mn = fmaxf(m_st[i][hf], tm);
                scf[i][hf] = __expf(m_st[i][hf] - mn);
                m_st[i][hf] = mn;
            }

        // ---- P = exp(S - m), write bf16 to smem, partial rowsums ----
        float rs0[4] = {0.f, 0.f, 0.f, 0.f}, rs1[4] = {0.f, 0.f, 0.f, 0.f};
        uint32_t* UP = (uint32_t*)Ps;
#pragma unroll
        for (int i = 0; i < 4; i++) {
#pragma unroll
            for (int j = 0; j < 4; j++) {
                float p0 = __expf(sacc[i][j][0] - m_st[i][0]);
                float p1 = __expf(sacc[i][j][1] - m_st[i][0]);
                float p2 = __expf(sacc[i][j][2] - m_st[i][1]);
                float p3 = __expf(sacc[i][j][3] - m_st[i][1]);
                rs0[i] += p0 + p1;
                rs1[i] += p2 + p3;
                int cu = ((wn + j * 8) >> 1) + cq;
                UP[(wm + i * 16 + rq) * 68 + cu]     = pack_bf16(p0, p1);
                UP[(wm + i * 16 + rq + 8) * 68 + cu] = pack_bf16(p2, p3);
            }
        }
#pragma unroll
        for (int i = 0; i < 4; i++) {
            float a = rs0[i];
            a += __shfl_xor_sync(0xffffffffu, a, 1);
            a += __shfl_xor_sync(0xffffffffu, a, 2);
            float bb = rs1[i];
            bb += __shfl_xor_sync(0xffffffffu, bb, 1);
            bb += __shfl_xor_sync(0xffffffffu, bb, 2);
            if (cq == 0) {
                reds[g * 128 + wm + i * 16 + rq]     = a;
                reds[g * 128 + wm + i * 16 + rq + 8] = bb;
            }
        }
        __syncthreads();

        // ---- l update + O rescale ----
#pragma unroll
        for (int i = 0; i < 4; i++)
#pragma unroll
            for (int hf = 0; hf < 2; hf++) {
                int r = wm + i * 16 + rq + hf * 8;
                float ts = reds[r] + reds[128 + r] + reds[256 + r] + reds[384 + r];
                l_st[i][hf] = l_st[i][hf] * scf[i][hf] + ts;
            }
#pragma unroll
        for (int i = 0; i < 4; i++)
#pragma unroll
            for (int j = 0; j < 4; j++) {
                oacc[i][j][0] *= scf[i][0];
                oacc[i][j][1] *= scf[i][0];
                oacc[i][j][2] *= scf[i][1];
                oacc[i][j][3] *= scf[i][1];
            }

        // ---- O += P·V  (M=128 q, N=128 d, K=128 s) ----
        const uint32_t* UPc = (const uint32_t*)Ps;
        const uint32_t* UV  = (const uint32_t*)(Vs + cur * 128 * FVS);
#pragma unroll
        for (int ks = 0; ks < 8; ks++) {
            int kk = ks * 8;
            uint32_t afr[4][4];
#pragma unroll
            for (int i = 0; i < 4; i++) {
                int r0 = wm + i * 16 + rq;
                afr[i][0] = UPc[r0 * 68 + kk + cq];
                afr[i][1] = UPc[(r0 + 8) * 68 + kk + cq];
                afr[i][2] = UPc[r0 * 68 + kk + 4 + cq];
                afr[i][3] = UPc[(r0 + 8) * 68 + kk + 4 + cq];
            }
            uint32_t bfr[4][2];
#pragma unroll
            for (int j = 0; j < 4; j++) {
                int n0 = wn + j * 8 + rq;
                bfr[j][0] = UV[n0 * 68 + kk + cq];
                bfr[j][1] = UV[n0 * 68 + kk + 4 + cq];
            }
#pragma unroll
            for (int i = 0; i < 4; i++)
#pragma unroll
                for (int j = 0; j < 4; j++)
                    mma16816(oacc[i][j], afr[i], bfr[j]);
        }
        cur ^= 1;
    }

    // ---- epilogue: O / l -> ob (bf16) ----
#pragma unroll
    for (int i = 0; i < 4; i++) {
        float inv0 = 1.f / l_st[i][0];
        float inv1 = 1.f / l_st[i][1];
#pragma unroll
        for (int j = 0; j < 4; j++) {
            int row = b * 1024 + qt * 128 + wm + i * 16 + rq;
            int col = h * 512 + dch * 128 + wn + j * 8 + cq2;
            *reinterpret_cast<uint32_t*>(Og + (size_t)row * 4096 + col) =
                pack_bf16(oacc[i][j][0] * inv0, oacc[i][j][1] * inv0);
            *reinterpret_cast<uint32_t*>(Og + (size_t)(row + 8) * 4096 + col) =
                pack_bf16(oacc[i][j][2] * inv1, oacc[i][j][3] * inv1);
        }
    }
}

// -------- LayerNorm over D=512, eps=1e-6 --------
__global__ void layernorm_k(const float* __restrict__ y, const float* __restrict__ gamma,
                            const float* __restrict__ beta, float* __restrict__ out) {
    int row = blockIdx.x;
    int t = threadIdx.x;
    const float4* p = reinterpret_cast<const float4*>(y + (size_t)row * 512);
    float4 v = p[t];
    float s = v.x + v.y + v.z + v.w;
#pragma unroll
    for (int o = 16; o; o >>= 1) s += __shfl_xor_sync(0xffffffffu, s, o);
    __shared__ float sm[4];
    if ((t & 31) == 0) sm[t >> 5] = s;
    __syncthreads();
    float mu = (sm[0] + sm[1] + sm[2] + sm[3]) * (1.0f / 512.0f);
    float dx = v.x - mu, dy = v.y - mu, dz = v.z - mu, dw = v.w - mu;
    float q = dx * dx + dy * dy + dz * dz + dw * dw;
#pragma unroll
    for (int o = 16; o; o >>= 1) q += __shfl_xor_sync(0xffffffffu, q, o);
    __shared__ float sq[4];
    if ((t & 31) == 0) sq[t >> 5] = q;
    __syncthreads();
    float var = (sq[0] + sq[1] + sq[2] + sq[3]) * (1.0f / 512.0f);
    float rs = rsqrtf(var + 1e-6f);
    float4 g = reinterpret_cast<const float4*>(gamma)[t];
    float4 b = reinterpret_cast<const float4*>(beta)[t];
    float4 r;
    r.x = dx * rs * g.x + b.x;
    r.y = dy * rs * g.y + b.y;
    r.z = dz * rs * g.z + b.z;
    r.w = dw * rs * g.w + b.w;
    reinterpret_cast<float4*>(out + (size_t)row * 512)[t] = r;
}

// ---------------------------------------------------------------
extern "C" void kernel_launch(void* const* d_in, const int* in_sizes, int n_in,
                              void* d_out, int out_size) {
    const float* x     = (const float*)d_in[0];
    const float* Wq    = (const float*)d_in[1];
    const float* Wk    = (const float*)d_in[2];
    const float* Wv    = (const float*)d_in[3];
    const float* Wo    = (const float*)d_in[4];
    const float* bo    = (const float*)d_in[5];
    const float* gamma = (const float*)d_in[6];
    const float* beta  = (const float*)d_in[7];
    float* out = (float*)d_out;

    bf16 *xb, *qb, *kb, *wqt, *wkt, *wvt, *wot, *vt, *ob;
    float *yb;
    cudaGetSymbolAddress((void**)&xb,  g_xb);
    cudaGetSymbolAddress((void**)&qb,  g_qb);
    cudaGetSymbolAddress((void**)&kb,  g_kb);
    cudaGetSymbolAddress((void**)&wqt, g_wqt);
    cudaGetSymbolAddress((void**)&wkt, g_wkt);
    cudaGetSymbolAddress((void**)&wvt, g_wvt);
    cudaGetSymbolAddress((void**)&wot, g_wot);
    cudaGetSymbolAddress((void**)&vt,  g_vt);
    cudaGetSymbolAddress((void**)&ob,  g_ob);
    cudaGetSymbolAddress((void**)&yb,  g_y);

    cudaFuncSetAttribute(flash_attn_k, cudaFuncAttributeMaxDynamicSharedMemorySize, FLASH_SMEM);

    // 1) x -> bf16
    f32_to_bf16_k<<<(int)(SZ_X / 4 / 256), 256>>>(x, xb, (int)SZ_X);
    // 2) transposed bf16 weights
    transpose_to_bf16<<<dim3(16, 16),  dim3(32, 8)>>>(Wq, wqt, 512, 512);
    transpose_to_bf16<<<dim3(16, 16),  dim3(32, 8)>>>(Wk, wkt, 512, 512);
    transpose_to_bf16<<<dim3(128, 16), dim3(32, 8)>>>(Wv, wvt, 512, 4096);
    transpose_to_bf16<<<dim3(16, 128), dim3(32, 8)>>>(Wo, wot, 4096, 512);

    // 3) q = x @ Wq   [8192,512]
    gemm_bf16_tn<1><<<dim3(4, 64, 1), 256>>>(xb, wqt, qb, 8192, 512, 512,
        512, 512, 512, 0, 0, 0, 0, 0, 0, 1, 1.0f, nullptr, nullptr, 0);
    // 4) k = x @ Wk
    gemm_bf16_tn<1><<<dim3(4, 64, 1), 256>>>(xb, wkt, kb, 8192, 512, 512,
        512, 512, 512, 0, 0, 0, 0, 0, 0, 1, 1.0f, nullptr, nullptr, 0);
    // 5) Vt[b] = WvT @ x[b]^T  -> [b][4096][1024]
    gemm_bf16_tn<1><<<dim3(8, 32, 8), 256>>>(wvt, xb, vt, 4096, 1024, 512,
        512, 512, 1024, 0, 0, 0, 524288LL, 0, 4194304LL, 1, 1.0f, nullptr, nullptr, 0);
    // 6) fused attention: scores + mask + softmax + P·V -> ob
    flash_attn_k<<<dim3(32, 64), 256, FLASH_SMEM>>>(qb, kb, vt, ob);
    // 7) y = o @ Wo + bo + x
    gemm_bf16_tn<2><<<dim3(4, 64, 1), 256>>>(ob, wot, yb, 8192, 512, 4096,
        4096, 4096, 512, 0, 0, 0, 0, 0, 0, 1, 1.0f, bo, x, 512);
    // 8) LayerNorm -> out
    layernorm_k<<<8192, 128>>>(yb, gamma, beta, out);
}

// round 5
// speedup vs baseline: 1.0758x; 1.0375x over previous
#include <cuda_runtime.h>
#include <cuda_bf16.h>
#include <cstdint>

using bf16 = __nv_bfloat16;

// Problem dims
static constexpr int NB = 8, NS = 1024, ND = 512, NK = 64, NH = 8;

static constexpr size_t SZ_X  = (size_t)NB * NS * ND;          // 4,194,304
static constexpr size_t SZ_VT = (size_t)NB * (ND * NH) * NS;   // 33,554,432
static constexpr size_t SZ_O  = (size_t)NB * NS * (NH * ND);   // 33,554,432

// -------- static scratch (no runtime allocation allowed) --------
__device__ bf16  g_xb [SZ_X];
__device__ bf16  g_qb [SZ_X];
__device__ bf16  g_kb [SZ_X];
__device__ bf16  g_wqt[ND * (NK * NH)];   // [512][512]  WqT
__device__ bf16  g_wkt[ND * (NK * NH)];   // [512][512]  WkT
__device__ bf16  g_wvt[(ND * NH) * ND];   // [4096][512] WvT
__device__ bf16  g_wot[ND * (ND * NH)];   // [512][4096] WoT
__device__ bf16  g_vt [SZ_VT];            // [b][4096][1024]  V^T per batch
__device__ bf16  g_ob [SZ_O];             // [8192][4096] attention output
__device__ float g_y  [SZ_X];             // pre-LN (o@Wo + bo + x)

// ---------------------------------------------------------------
__device__ __forceinline__ uint32_t pack_bf16(float lo, float hi) {
    return ((uint32_t)__bfloat16_as_ushort(__float2bfloat16(hi)) << 16) |
            (uint32_t)__bfloat16_as_ushort(__float2bfloat16(lo));
}

__device__ __forceinline__ void mma16816(float* d, const uint32_t* a, const uint32_t* b) {
    asm volatile(
        "mma.sync.aligned.m16n8k16.row.col.f32.bf16.bf16.f32 "
        "{%0,%1,%2,%3}, {%4,%5,%6,%7}, {%8,%9}, {%0,%1,%2,%3};\n"
        : "+f"(d[0]), "+f"(d[1]), "+f"(d[2]), "+f"(d[3])
        : "r"(a[0]), "r"(a[1]), "r"(a[2]), "r"(a[3]), "r"(b[0]), "r"(b[1]));
}

__device__ __forceinline__ void cpasync16(void* s, const void* g) {
    uint32_t sa = (uint32_t)__cvta_generic_to_shared(s);
    asm volatile("cp.async.cg.shared.global [%0], [%1], 16;\n" :: "r"(sa), "l"(g));
}
__device__ __forceinline__ void cpcommit() { asm volatile("cp.async.commit_group;\n" ::: "memory"); }
__device__ __forceinline__ void cpwait0()  { asm volatile("cp.async.wait_group 0;\n" ::: "memory"); }
__device__ __forceinline__ void cpwait1()  { asm volatile("cp.async.wait_group 1;\n" ::: "memory"); }

// -------- elementwise convert fp32 -> bf16 --------
__global__ void f32_to_bf16_k(const float* __restrict__ in, bf16* __restrict__ out, int n) {
    int i = (blockIdx.x * blockDim.x + threadIdx.x) * 4;
    if (i >= n) return;
    float4 v = *reinterpret_cast<const float4*>(in + i);
    uint2 u;
    u.x = pack_bf16(v.x, v.y);
    u.y = pack_bf16(v.z, v.w);
    *reinterpret_cast<uint2*>(out + i) = u;
}

// -------- transpose + convert: out[c][r] = in[r][c] --------
__global__ void transpose_to_bf16(const float* __restrict__ in, bf16* __restrict__ out,
                                  int R, int C) {
    __shared__ float t[32][33];
    int c0 = blockIdx.x * 32, r0 = blockIdx.y * 32;
    int tx = threadIdx.x;
    for (int i = threadIdx.y; i < 32; i += 8)
        t[i][tx] = in[(size_t)(r0 + i) * C + c0 + tx];
    __syncthreads();
    for (int i = threadIdx.y; i < 32; i += 8)
        out[(size_t)(c0 + i) * R + r0 + tx] = __float2bfloat16(t[tx][i]);
}

// -------- generic batched bf16 GEMM (cp.async double-buffered) --------
// C[m,n] = alpha * sum_k A[m,k] * B[n,k]
// MODE 1: bf16 store     MODE 2: fp32 store + bias[n] + resid[m,n]
#define BM 128
#define BN 128
#define BK 32
#define BKP 40   // padded smem row (bf16) -> 20 uint32, conflict-free

template <int MODE>
__global__ __launch_bounds__(256, 2)
void gemm_bf16_tn(const bf16* __restrict__ A, const bf16* __restrict__ B,
                  void* __restrict__ Cv,
                  int M, int N, int Kd, int lda, int ldb, int ldc,
                  long long sA1, long long sA2, long long sB1, long long sB2,
                  long long sC1, long long sC2, int Z1,
                  float alpha, const float* __restrict__ bias,
                  const float* __restrict__ resid, int ldres) {
    int z = blockIdx.z;
    int z1 = z % Z1, z2 = z / Z1;
    A += (size_t)z1 * sA1 + (size_t)z2 * sA2;
    B += (size_t)z1 * sB1 + (size_t)z2 * sB2;
    long long coff = (long long)z1 * sC1 + (long long)z2 * sC2;

    __shared__ alignas(16) bf16 As[2][BM][BKP];
    __shared__ alignas(16) bf16 Bs[2][BN][BKP];

    int tid  = threadIdx.x;
    int warp = tid >> 5, lane = tid & 31;
    int wm = (warp & 1) * 64;
    int wn = (warp >> 1) * 32;
    int bm0 = blockIdx.y * BM;
    int bn0 = blockIdx.x * BN;

    float acc[4][4][4];
#pragma unroll
    for (int i = 0; i < 4; i++)
#pragma unroll
        for (int j = 0; j < 4; j++)
#pragma unroll
            for (int r = 0; r < 4; r++) acc[i][j][r] = 0.f;

    int lr = tid >> 2;
    int lc = (tid & 3) * 8;
    int rq = lane >> 2;
    int cq = lane & 3;

#pragma unroll
    for (int i = 0; i < 2; i++) {
        int r = lr + i * 64;
        cpasync16(&As[0][r][lc], A + (size_t)(bm0 + r) * lda + lc);
        cpasync16(&Bs[0][r][lc], B + (size_t)(bn0 + r) * ldb + lc);
    }
    cpcommit();

    int p = 0;
    for (int kt = 0; kt < Kd; kt += BK, p ^= 1) {
        cpwait0();
        __syncthreads();
        if (kt + BK < Kd) {
            int np = p ^ 1;
#pragma unroll
            for (int i = 0; i < 2; i++) {
                int r = lr + i * 64;
                cpasync16(&As[np][r][lc], A + (size_t)(bm0 + r) * lda + kt + BK + lc);
                cpasync16(&Bs[np][r][lc], B + (size_t)(bn0 + r) * ldb + kt + BK + lc);
            }
            cpcommit();
        }

        const uint32_t* UA = reinterpret_cast<const uint32_t*>(&As[p][0][0]);
        const uint32_t* UB = reinterpret_cast<const uint32_t*>(&Bs[p][0][0]);
#pragma unroll
        for (int ks = 0; ks < 2; ks++) {
            int kk = ks * 8;
            uint32_t afr[4][4];
#pragma unroll
            for (int i = 0; i < 4; i++) {
                int r0 = wm + i * 16 + rq;
                afr[i][0] = UA[r0 * 20 + kk + cq];
                afr[i][1] = UA[(r0 + 8) * 20 + kk + cq];
                afr[i][2] = UA[r0 * 20 + kk + 4 + cq];
                afr[i][3] = UA[(r0 + 8) * 20 + kk + 4 + cq];
            }
            uint32_t bfr[4][2];
#pragma unroll
            for (int j = 0; j < 4; j++) {
                int n0 = wn + j * 8 + rq;
                bfr[j][0] = UB[n0 * 20 + kk + cq];
                bfr[j][1] = UB[n0 * 20 + kk + 4 + cq];
            }
#pragma unroll
            for (int i = 0; i < 4; i++)
#pragma unroll
                for (int j = 0; j < 4; j++)
                    mma16816(acc[i][j], afr[i], bfr[j]);
        }
        __syncthreads();
    }

    int cq2 = cq * 2;
    float* Cf = (MODE == 1) ? nullptr : (float*)Cv + coff;
    bf16*  Cb = (MODE == 1) ? (bf16*)Cv + coff : nullptr;
#pragma unroll
    for (int i = 0; i < 4; i++) {
#pragma unroll
        for (int j = 0; j < 4; j++) {
            int row = bm0 + wm + i * 16 + rq;
            int col = bn0 + wn + j * 8 + cq2;
            float c0 = acc[i][j][0] * alpha, c1 = acc[i][j][1] * alpha;
            float c2 = acc[i][j][2] * alpha, c3 = acc[i][j][3] * alpha;
            if (MODE == 2) {
                float b0v = bias[col], b1v = bias[col + 1];
                const float* r0p = resid + (size_t)row * ldres + col;
                const float* r1p = resid + (size_t)(row + 8) * ldres + col;
                c0 += b0v + r0p[0]; c1 += b1v + r0p[1];
                c2 += b0v + r1p[0]; c3 += b1v + r1p[1];
            }
            if (MODE == 1) {
                *reinterpret_cast<uint32_t*>(Cb + (size_t)row * ldc + col)       = pack_bf16(c0, c1);
                *reinterpret_cast<uint32_t*>(Cb + (size_t)(row + 8) * ldc + col) = pack_bf16(c2, c3);
            } else {
                *reinterpret_cast<float2*>(Cf + (size_t)row * ldc + col)       = make_float2(c0, c1);
                *reinterpret_cast<float2*>(Cf + (size_t)(row + 8) * ldc + col) = make_float2(c2, c3);
            }
        }
    }
}

// ================================================================
// Fused flash attention, FA2-style warp layout: each warp owns 16
// complete query rows -> softmax is quad-shuffle-only, P stays in
// registers (C-frag of S == A-frag of P·V). One syncthreads/iter.
// Block: q-tile 128 x d-chunk 128 for one (b,h); 8 s-iters of 128.
// grid = (32, 64): x = dch*8 + qt, y = b*8 + h.
// Smem: Q[128*72] | K[2][128*72] | V[2][128*136]   (~122 KB)
// ================================================================
static constexpr int FQS = 72;    // Q/K row stride bf16 (36 u32)
static constexpr int FVS = 136;   // V row stride bf16 (68 u32)
static constexpr int FLASH_SMEM = (128 * FQS * 3 + 2 * 128 * FVS) * 2;

__global__ __launch_bounds__(256, 1)
void flash_attn_k(const bf16* __restrict__ Qg, const bf16* __restrict__ Kg,
                  const bf16* __restrict__ Vg, bf16* __restrict__ Og) {
    extern __shared__ __align__(16) char fsm[];
    bf16* Qs = (bf16*)fsm;           // 128*72
    bf16* Ks = Qs + 128 * FQS;       // 2 bufs of 128*72
    bf16* Vs = Ks + 2 * 128 * FQS;   // 2 bufs of 128*136

    int tid  = threadIdx.x;
    int warp = tid >> 5, lane = tid & 31;
    int rq = lane >> 2, cq = lane & 3, cq2 = cq << 1;
    int w16 = warp * 16;
    int qt = blockIdx.x & 7, dch = blockIdx.x >> 3;
    int b  = blockIdx.y >> 3, h = blockIdx.y & 7;

    const bf16* Qp = Qg + ((size_t)(b * 1024 + qt * 128)) * 512 + h * 64;
    const bf16* Kp = Kg + ((size_t)(b * 1024)) * 512 + h * 64;
    const bf16* Vp = Vg + (size_t)b * 4194304 + ((size_t)(h * 512 + dch * 128)) * 1024;

    // Q in its own commit group, then K0/V0
#pragma unroll
    for (int p = 0; p < 4; p++) {
        int idx = tid + p * 256; int r = idx >> 3, c = (idx & 7) * 8;
        cpasync16(Qs + r * FQS + c, Qp + (size_t)r * 512 + c);
    }
    cpcommit();
#pragma unroll
    for (int p = 0; p < 4; p++) {
        int idx = tid + p * 256; int r = idx >> 3, c = (idx & 7) * 8;
        cpasync16(Ks + r * FQS + c, Kp + (size_t)r * 512 + c);
    }
#pragma unroll
    for (int p = 0; p < 8; p++) {
        int idx = tid + p * 256; int r = idx >> 4, c = (idx & 15) * 8;
        cpasync16(Vs + r * FVS + c, Vp + (size_t)r * 1024 + c);
    }
    cpcommit();

    // Q fragments -> registers (once)
    cpwait1();               // Q group done (K/V may still be in flight)
    __syncthreads();
    uint32_t qfr[4][4];
    {
        const uint32_t* UQ = (const uint32_t*)Qs;
#pragma unroll
        for (int kg = 0; kg < 4; kg++) {
            qfr[kg][0] = UQ[(w16 + rq) * 36 + kg * 8 + cq];
            qfr[kg][1] = UQ[(w16 + rq + 8) * 36 + kg * 8 + cq];
            qfr[kg][2] = UQ[(w16 + rq) * 36 + kg * 8 + 4 + cq];
            qfr[kg][3] = UQ[(w16 + rq + 8) * 36 + kg * 8 + 4 + cq];
        }
    }

    float oacc[16][4];
#pragma unroll
    for (int n = 0; n < 16; n++)
#pragma unroll
        for (int r = 0; r < 4; r++) oacc[n][r] = 0.f;
    float m0 = -1e30f, m1 = -1e30f, l0 = 0.f, l1 = 0.f;

    int cur = 0;
    for (int st = 0; st < 8; st++) {
        cpwait0();
        __syncthreads();
        if (st < 7) {
            int nb = cur ^ 1;
            int s1 = (st + 1) * 128;
#pragma unroll
            for (int p = 0; p < 4; p++) {
                int idx = tid + p * 256; int r = idx >> 3, c = (idx & 7) * 8;
                cpasync16(Ks + nb * 128 * FQS + r * FQS + c, Kp + (size_t)(s1 + r) * 512 + c);
            }
#pragma unroll
            for (int p = 0; p < 8; p++) {
                int idx = tid + p * 256; int r = idx >> 4, c = (idx & 15) * 8;
                cpasync16(Vs + nb * 128 * FVS + r * FVS + c, Vp + (size_t)r * 1024 + s1 + c);
            }
            cpcommit();
        }

        // ---- S = Q·K^T : M=16 (warp rows), N=128, K=64 ----
        float sacc[16][4];
#pragma unroll
        for (int j = 0; j < 16; j++)
#pragma unroll
            for (int r = 0; r < 4; r++) sacc[j][r] = 0.f;

        const uint32_t* UK = (const uint32_t*)(Ks + cur * 128 * FQS);
#pragma unroll
        for (int kg = 0; kg < 4; kg++) {
#pragma unroll
            for (int j = 0; j < 16; j++) {
                uint32_t bfr[2];
                bfr[0] = UK[(j * 8 + rq) * 36 + kg * 8 + cq];
                bfr[1] = UK[(j * 8 + rq) * 36 + kg * 8 + 4 + cq];
                mma16816(sacc[j], qfr[kg], bfr);
            }
        }

        // mask (raw==0) + scale 1/8
#pragma unroll
        for (int j = 0; j < 16; j++)
#pragma unroll
            for (int r = 0; r < 4; r++) {
                float v = sacc[j][r];
                sacc[j][r] = (v == 0.f) ? -1e9f : v * 0.125f;
            }

        // ---- row max (quad shuffle only) ----
        float mx0 = -1e30f, mx1 = -1e30f;
#pragma unroll
        for (int j = 0; j < 16; j++) {
            mx0 = fmaxf(mx0, fmaxf(sacc[j][0], sacc[j][1]));
            mx1 = fmaxf(mx1, fmaxf(sacc[j][2], sacc[j][3]));
        }
        mx0 = fmaxf(mx0, __shfl_xor_sync(0xffffffffu, mx0, 1));
        mx0 = fmaxf(mx0, __shfl_xor_sync(0xffffffffu, mx0, 2));
        mx1 = fmaxf(mx1, __shfl_xor_sync(0xffffffffu, mx1, 1));
        mx1 = fmaxf(mx1, __shfl_xor_sync(0xffffffffu, mx1, 2));

        float nm0 = fmaxf(m0, mx0), nm1 = fmaxf(m1, mx1);
        float scf0 = __expf(m0 - nm0), scf1 = __expf(m1 - nm1);
        m0 = nm0; m1 = nm1;

#pragma unroll
        for (int n = 0; n < 16; n++) {
            oacc[n][0] *= scf0; oacc[n][1] *= scf0;
            oacc[n][2] *= scf1; oacc[n][3] *= scf1;
        }

        // ---- P = exp(S-m) in registers + rowsum ----
        uint32_t pf[8][4];
        float rs0 = 0.f, rs1 = 0.f;
#pragma unroll
        for (int kg = 0; kg < 8; kg++) {
            int j0 = 2 * kg, j1 = 2 * kg + 1;
            float e00 = __expf(sacc[j0][0] - m0), e01 = __expf(sacc[j0][1] - m0);
            float e02 = __expf(sacc[j0][2] - m1), e03 = __expf(sacc[j0][3] - m1);
            float e10 = __expf(sacc[j1][0] - m0), e11 = __expf(sacc[j1][1] - m0);
            float e12 = __expf(sacc[j1][2] - m1), e13 = __expf(sacc[j1][3] - m1);
            rs0 += e00 + e01 + e10 + e11;
            rs1 += e02 + e03 + e12 + e13;
            pf[kg][0] = pack_bf16(e00, e01);
            pf[kg][1] = pack_bf16(e02, e03);
            pf[kg][2] = pack_bf16(e10, e11);
            pf[kg][3] = pack_bf16(e12, e13);
        }
        rs0 += __shfl_xor_sync(0xffffffffu, rs0, 1);
        rs0 += __shfl_xor_sync(0xffffffffu, rs0, 2);
        rs1 += __shfl_xor_sync(0xffffffffu, rs1, 1);
        rs1 += __shfl_xor_sync(0xffffffffu, rs1, 2);
        l0 = l0 * scf0 + rs0;
        l1 = l1 * scf1 + rs1;

        // ---- O += P·V : M=16, N=128 (d), K=128 (s) ----
        const uint32_t* UV = (const uint32_t*)(Vs + cur * 128 * FVS);
#pragma unroll
        for (int n = 0; n < 16; n++) {
#pragma unroll
            for (int kg = 0; kg < 8; kg++) {
                uint32_t bfr[2];
                bfr[0] = UV[(n * 8 + rq) * 68 + kg * 8 + cq];
                bfr[1] = UV[(n * 8 + rq) * 68 + kg * 8 + 4 + cq];
                mma16816(oacc[n], pf[kg], bfr);
            }
        }
        cur ^= 1;
    }

    // ---- epilogue: O / l -> ob (bf16) ----
    float inv0 = 1.f / l0, inv1 = 1.f / l1;
    int row = b * 1024 + qt * 128 + w16 + rq;
    int colb = h * 512 + dch * 128 + cq2;
#pragma unroll
    for (int n = 0; n < 16; n++) {
        int col = colb + n * 8;
        *reinterpret_cast<uint32_t*>(Og + (size_t)row * 4096 + col) =
            pack_bf16(oacc[n][0] * inv0, oacc[n][1] * inv0);
        *reinterpret_cast<uint32_t*>(Og + (size_t)(row + 8) * 4096 + col) =
            pack_bf16(oacc[n][2] * inv1, oacc[n][3] * inv1);
    }
}

// -------- LayerNorm over D=512, eps=1e-6 --------
__global__ void layernorm_k(const float* __restrict__ y, const float* __restrict__ gamma,
                            const float* __restrict__ beta, float* __restrict__ out) {
    int row = blockIdx.x;
    int t = threadIdx.x;
    const float4* p = reinterpret_cast<const float4*>(y + (size_t)row * 512);
    float4 v = p[t];
    float s = v.x + v.y + v.z + v.w;
#pragma unroll
    for (int o = 16; o; o >>= 1) s += __shfl_xor_sync(0xffffffffu, s, o);
    __shared__ float sm[4];
    if ((t & 31) == 0) sm[t >> 5] = s;
    __syncthreads();
    float mu = (sm[0] + sm[1] + sm[2] + sm[3]) * (1.0f / 512.0f);
    float dx = v.x - mu, dy = v.y - mu, dz = v.z - mu, dw = v.w - mu;
    float q = dx * dx + dy * dy + dz * dz + dw * dw;
#pragma unroll
    for (int o = 16; o; o >>= 1) q += __shfl_xor_sync(0xffffffffu, q, o);
    __shared__ float sq[4];
    if ((t & 31) == 0) sq[t >> 5] = q;
    __syncthreads();
    float var = (sq[0] + sq[1] + sq[2] + sq[3]) * (1.0f / 512.0f);
    float rs = rsqrtf(var + 1e-6f);
    float4 g = reinterpret_cast<const float4*>(gamma)[t];
    float4 b = reinterpret_cast<const float4*>(beta)[t];
    float4 r;
    r.x = dx * rs * g.x + b.x;
    r.y = dy * rs * g.y + b.y;
    r.z = dz * rs * g.z + b.z;
    r.w = dw * rs * g.w + b.w;
    reinterpret_cast<float4*>(out + (size_t)row * 512)[t] = r;
}

// ---------------------------------------------------------------
extern "C" void kernel_launch(void* const* d_in, const int* in_sizes, int n_in,
                              void* d_out, int out_size) {
    const float* x     = (const float*)d_in[0];
    const float* Wq    = (const float*)d_in[1];
    const float* Wk    = (const float*)d_in[2];
    const float* Wv    = (const float*)d_in[3];
    const float* Wo    = (const float*)d_in[4];
    const float* bo    = (const float*)d_in[5];
    const float* gamma = (const float*)d_in[6];
    const float* beta  = (const float*)d_in[7];
    float* out = (float*)d_out;

    bf16 *xb, *qb, *kb, *wqt, *wkt, *wvt, *wot, *vt, *ob;
    float *yb;
    cudaGetSymbolAddress((void**)&xb,  g_xb);
    cudaGetSymbolAddress((void**)&qb,  g_qb);
    cudaGetSymbolAddress((void**)&kb,  g_kb);
    cudaGetSymbolAddress((void**)&wqt, g_wqt);
    cudaGetSymbolAddress((void**)&wkt, g_wkt);
    cudaGetSymbolAddress((void**)&wvt, g_wvt);
    cudaGetSymbolAddress((void**)&wot, g_wot);
    cudaGetSymbolAddress((void**)&vt,  g_vt);
    cudaGetSymbolAddress((void**)&ob,  g_ob);
    cudaGetSymbolAddress((void**)&yb,  g_y);

    cudaFuncSetAttribute(flash_attn_k, cudaFuncAttributeMaxDynamicSharedMemorySize, FLASH_SMEM);

    // 1) x -> bf16
    f32_to_bf16_k<<<(int)(SZ_X / 4 / 256), 256>>>(x, xb, (int)SZ_X);
    // 2) transposed bf16 weights
    transpose_to_bf16<<<dim3(16, 16),  dim3(32, 8)>>>(Wq, wqt, 512, 512);
    transpose_to_bf16<<<dim3(16, 16),  dim3(32, 8)>>>(Wk, wkt, 512, 512);
    transpose_to_bf16<<<dim3(128, 16), dim3(32, 8)>>>(Wv, wvt, 512, 4096);
    transpose_to_bf16<<<dim3(16, 128), dim3(32, 8)>>>(Wo, wot, 4096, 512);

    // 3) q = x @ Wq   [8192,512]
    gemm_bf16_tn<1><<<dim3(4, 64, 1), 256>>>(xb, wqt, qb, 8192, 512, 512,
        512, 512, 512, 0, 0, 0, 0, 0, 0, 1, 1.0f, nullptr, nullptr, 0);
    // 4) k = x @ Wk
    gemm_bf16_tn<1><<<dim3(4, 64, 1), 256>>>(xb, wkt, kb, 8192, 512, 512,
        512, 512, 512, 0, 0, 0, 0, 0, 0, 1, 1.0f, nullptr, nullptr, 0);
    // 5) Vt[b] = WvT @ x[b]^T  -> [b][4096][1024]
    gemm_bf16_tn<1><<<dim3(8, 32, 8), 256>>>(wvt, xb, vt, 4096, 1024, 512,
        512, 512, 1024, 0, 0, 0, 524288LL, 0, 4194304LL, 1, 1.0f, nullptr, nullptr, 0);
    // 6) fused attention: scores + mask + softmax + P·V -> ob
    flash_attn_k<<<dim3(32, 64), 256, FLASH_SMEM>>>(qb, kb, vt, ob);
    // 7) y = o @ Wo + bo + x
    gemm_bf16_tn<2><<<dim3(4, 64, 1), 256>>>(ob, wot, yb, 8192, 512, 4096,
        4096, 4096, 512, 0, 0, 0, 0, 0, 0, 1, 1.0f, bo, x, 512);
    // 8) LayerNorm -> out
    layernorm_k<<<8192, 128>>>(yb, gamma, beta, out);
}

// round 8
// speedup vs baseline: 1.1473x; 1.0665x over previous
#include <cuda_runtime.h>
#include <cuda_bf16.h>
#include <cstdint>

using bf16 = __nv_bfloat16;

// Problem dims
static constexpr int NB = 8, NS = 1024, ND = 512, NK = 64, NH = 8;

static constexpr size_t SZ_X  = (size_t)NB * NS * ND;          // 4,194,304
static constexpr size_t SZ_VT = (size_t)NB * (ND * NH) * NS;   // 33,554,432
static constexpr size_t SZ_O  = (size_t)NB * NS * (NH * ND);   // 33,554,432

// -------- static scratch (no runtime allocation allowed) --------
__device__ bf16  g_xb [SZ_X];
__device__ bf16  g_qb [SZ_X];
__device__ bf16  g_kb [SZ_X];
__device__ bf16  g_wqt[ND * (NK * NH)];   // [512][512]  WqT
__device__ bf16  g_wkt[ND * (NK * NH)];   // [512][512]  WkT
__device__ bf16  g_wvt[(ND * NH) * ND];   // [4096][512] WvT
__device__ bf16  g_wot[ND * (ND * NH)];   // [512][4096] WoT
__device__ bf16  g_vt [SZ_VT];            // [b][4096][1024]  V^T per batch
__device__ bf16  g_ob [SZ_O];             // [8192][4096] attention output
__device__ float g_y  [SZ_X];             // pre-LN (o@Wo + bo + x)

// ---------------------------------------------------------------
__device__ __forceinline__ uint32_t pack_bf16(float lo, float hi) {
    return ((uint32_t)__bfloat16_as_ushort(__float2bfloat16(hi)) << 16) |
            (uint32_t)__bfloat16_as_ushort(__float2bfloat16(lo));
}

__device__ __forceinline__ void mma16816(float* d, const uint32_t* a, const uint32_t* b) {
    asm volatile(
        "mma.sync.aligned.m16n8k16.row.col.f32.bf16.bf16.f32 "
        "{%0,%1,%2,%3}, {%4,%5,%6,%7}, {%8,%9}, {%0,%1,%2,%3};\n"
        : "+f"(d[0]), "+f"(d[1]), "+f"(d[2]), "+f"(d[3])
        : "r"(a[0]), "r"(a[1]), "r"(a[2]), "r"(a[3]), "r"(b[0]), "r"(b[1]));
}

// ldmatrix x4: loads 4 8x8 bf16 matrices; per-lane row address in shared.
__device__ __forceinline__ void ldsm_x4(uint32_t& r0, uint32_t& r1, uint32_t& r2, uint32_t& r3,
                                        const void* p) {
    uint32_t a = (uint32_t)__cvta_generic_to_shared(p);
    asm volatile("ldmatrix.sync.aligned.m8n8.x4.shared.b16 {%0,%1,%2,%3}, [%4];"
                 : "=r"(r0), "=r"(r1), "=r"(r2), "=r"(r3) : "r"(a));
}

__device__ __forceinline__ void cpasync16(void* s, const void* g) {
    uint32_t sa = (uint32_t)__cvta_generic_to_shared(s);
    asm volatile("cp.async.cg.shared.global [%0], [%1], 16;\n" :: "r"(sa), "l"(g));
}
__device__ __forceinline__ void cpcommit() { asm volatile("cp.async.commit_group;\n" ::: "memory"); }
__device__ __forceinline__ void cpwait0()  { asm volatile("cp.async.wait_group 0;\n" ::: "memory"); }
__device__ __forceinline__ void cpwait1()  { asm volatile("cp.async.wait_group 1;\n" ::: "memory"); }

// -------- elementwise convert fp32 -> bf16 --------
__global__ void f32_to_bf16_k(const float* __restrict__ in, bf16* __restrict__ out, int n) {
    int i = (blockIdx.x * blockDim.x + threadIdx.x) * 4;
    if (i >= n) return;
    float4 v = *reinterpret_cast<const float4*>(in + i);
    uint2 u;
    u.x = pack_bf16(v.x, v.y);
    u.y = pack_bf16(v.z, v.w);
    *reinterpret_cast<uint2*>(out + i) = u;
}

// -------- transpose + convert: out[c][r] = in[r][c] --------
__global__ void transpose_to_bf16(const float* __restrict__ in, bf16* __restrict__ out,
                                  int R, int C) {
    __shared__ float t[32][33];
    int c0 = blockIdx.x * 32, r0 = blockIdx.y * 32;
    int tx = threadIdx.x;
    for (int i = threadIdx.y; i < 32; i += 8)
        t[i][tx] = in[(size_t)(r0 + i) * C + c0 + tx];
    __syncthreads();
    for (int i = threadIdx.y; i < 32; i += 8)
        out[(size_t)(c0 + i) * R + r0 + tx] = __float2bfloat16(t[tx][i]);
}

// -------- generic batched bf16 GEMM (cp.async double-buffered, ldmatrix frags) --------
// C[m,n] = alpha * sum_k A[m,k] * B[n,k]
// MODE 1: bf16 store     MODE 2: fp32 store + bias[n] + resid[m,n]
#define BM 128
#define BN 128
#define BK 32
#define BKP 40   // padded smem row (bf16); 80B row stride -> ldmatrix conflict-free

template <int MODE>
__global__ __launch_bounds__(256, 2)
void gemm_bf16_tn(const bf16* __restrict__ A, const bf16* __restrict__ B,
                  void* __restrict__ Cv,
                  int M, int N, int Kd, int lda, int ldb, int ldc,
                  long long sA1, long long sA2, long long sB1, long long sB2,
                  long long sC1, long long sC2, int Z1,
                  float alpha, const float* __restrict__ bias,
                  const float* __restrict__ resid, int ldres) {
    int z = blockIdx.z;
    int z1 = z % Z1, z2 = z / Z1;
    A += (size_t)z1 * sA1 + (size_t)z2 * sA2;
    B += (size_t)z1 * sB1 + (size_t)z2 * sB2;
    long long coff = (long long)z1 * sC1 + (long long)z2 * sC2;

    __shared__ alignas(16) bf16 As[2][BM][BKP];
    __shared__ alignas(16) bf16 Bs[2][BN][BKP];

    int tid  = threadIdx.x;
    int warp = tid >> 5, lane = tid & 31;
    int wm = (warp & 1) * 64;
    int wn = (warp >> 1) * 32;
    int bm0 = blockIdx.y * BM;
    int bn0 = blockIdx.x * BN;

    float acc[4][4][4];
#pragma unroll
    for (int i = 0; i < 4; i++)
#pragma unroll
        for (int j = 0; j < 4; j++)
#pragma unroll
            for (int r = 0; r < 4; r++) acc[i][j][r] = 0.f;

    int lr = tid >> 2;
    int lc = (tid & 3) * 8;
    int rq = lane >> 2;
    int cq = lane & 3;
    int l16 = lane & 15, lhi = (lane >> 4) * 8;   // ldmatrix row-in-tile / k-half

#pragma unroll
    for (int i = 0; i < 2; i++) {
        int r = lr + i * 64;
        cpasync16(&As[0][r][lc], A + (size_t)(bm0 + r) * lda + lc);
        cpasync16(&Bs[0][r][lc], B + (size_t)(bn0 + r) * ldb + lc);
    }
    cpcommit();

    int p = 0;
    for (int kt = 0; kt < Kd; kt += BK, p ^= 1) {
        cpwait0();
        __syncthreads();
        if (kt + BK < Kd) {
            int np = p ^ 1;
#pragma unroll
            for (int i = 0; i < 2; i++) {
                int r = lr + i * 64;
                cpasync16(&As[np][r][lc], A + (size_t)(bm0 + r) * lda + kt + BK + lc);
                cpasync16(&Bs[np][r][lc], B + (size_t)(bn0 + r) * ldb + kt + BK + lc);
            }
            cpcommit();
        }

#pragma unroll
        for (int ks = 0; ks < 2; ks++) {
            int kk = ks * 16 + lhi;   // bf16 element offset within row
            uint32_t afr[4][4];
#pragma unroll
            for (int i = 0; i < 4; i++)
                ldsm_x4(afr[i][0], afr[i][1], afr[i][2], afr[i][3],
                        &As[p][wm + i * 16 + l16][kk]);
            uint32_t bfr[4][2];
#pragma unroll
            for (int jp = 0; jp < 2; jp++) {
                uint32_t b0, b1, b2, b3;
                ldsm_x4(b0, b1, b2, b3, &Bs[p][wn + jp * 16 + l16][kk]);
                bfr[2 * jp][0] = b0; bfr[2 * jp][1] = b2;
                bfr[2 * jp + 1][0] = b1; bfr[2 * jp + 1][1] = b3;
            }
#pragma unroll
            for (int i = 0; i < 4; i++)
#pragma unroll
                for (int j = 0; j < 4; j++)
                    mma16816(acc[i][j], afr[i], bfr[j]);
        }
        __syncthreads();
    }

    int cq2 = cq * 2;
    float* Cf = (MODE == 1) ? nullptr : (float*)Cv + coff;
    bf16*  Cb = (MODE == 1) ? (bf16*)Cv + coff : nullptr;
#pragma unroll
    for (int i = 0; i < 4; i++) {
#pragma unroll
        for (int j = 0; j < 4; j++) {
            int row = bm0 + wm + i * 16 + rq;
            int col = bn0 + wn + j * 8 + cq2;
            float c0 = acc[i][j][0] * alpha, c1 = acc[i][j][1] * alpha;
            float c2 = acc[i][j][2] * alpha, c3 = acc[i][j][3] * alpha;
            if (MODE == 2) {
                float b0v = bias[col], b1v = bias[col + 1];
                const float* r0p = resid + (size_t)row * ldres + col;
                const float* r1p = resid + (size_t)(row + 8) * ldres + col;
                c0 += b0v + r0p[0]; c1 += b1v + r0p[1];
                c2 += b0v + r1p[0]; c3 += b1v + r1p[1];
            }
            if (MODE == 1) {
                *reinterpret_cast<uint32_t*>(Cb + (size_t)row * ldc + col)       = pack_bf16(c0, c1);
                *reinterpret_cast<uint32_t*>(Cb + (size_t)(row + 8) * ldc + col) = pack_bf16(c2, c3);
            } else {
                *reinterpret_cast<float2*>(Cf + (size_t)row * ldc + col)       = make_float2(c0, c1);
                *reinterpret_cast<float2*>(Cf + (size_t)(row + 8) * ldc + col) = make_float2(c2, c3);
            }
        }
    }
}

// ================================================================
// Fused flash attention, FA2-style warp layout + ldmatrix fragment
// loads. Each warp owns 16 complete query rows; softmax is
// quad-shuffle-only; P stays in registers. One syncthreads/iter.
// Block: q-tile 128 x d-chunk 128 for one (b,h); 8 s-iters of 128.
// grid = (32, 64): x = dch*8 + qt, y = b*8 + h.
// Smem: Q[128*72] | K[2][128*72] | V[2][128*136]   (~122 KB)
// ================================================================
static constexpr int FQS = 72;    // Q/K row stride bf16 (144B, 16B-aligned, conflict-free)
static constexpr int FVS = 136;   // V row stride bf16 (272B, 16B-aligned, conflict-free)
static constexpr int FLASH_SMEM = (128 * FQS * 3 + 2 * 128 * FVS) * 2;

__global__ __launch_bounds__(256, 1)
void flash_attn_k(const bf16* __restrict__ Qg, const bf16* __restrict__ Kg,
                  const bf16* __restrict__ Vg, bf16* __restrict__ Og) {
    extern __shared__ __align__(16) char fsm[];
    bf16* Qs = (bf16*)fsm;           // 128*72
    bf16* Ks = Qs + 128 * FQS;       // 2 bufs of 128*72
    bf16* Vs = Ks + 2 * 128 * FQS;   // 2 bufs of 128*136

    int tid  = threadIdx.x;
    int warp = tid >> 5, lane = tid & 31;
    int rq = lane >> 2, cq = lane & 3, cq2 = cq << 1;
    int l16 = lane & 15, lhi = (lane >> 4) * 8;
    int w16 = warp * 16;
    int qt = blockIdx.x & 7, dch = blockIdx.x >> 3;
    int b  = blockIdx.y >> 3, h = blockIdx.y & 7;

    const bf16* Qp = Qg + ((size_t)(b * 1024 + qt * 128)) * 512 + h * 64;
    const bf16* Kp = Kg + ((size_t)(b * 1024)) * 512 + h * 64;
    const bf16* Vp = Vg + (size_t)b * 4194304 + ((size_t)(h * 512 + dch * 128)) * 1024;

#pragma unroll
    for (int p = 0; p < 4; p++) {
        int idx = tid + p * 256; int r = idx >> 3, c = (idx & 7) * 8;
        cpasync16(Qs + r * FQS + c, Qp + (size_t)r * 512 + c);
    }
    cpcommit();
#pragma unroll
    for (int p = 0; p < 4; p++) {
        int idx = tid + p * 256; int r = idx >> 3, c = (idx & 7) * 8;
        cpasync16(Ks + r * FQS + c, Kp + (size_t)r * 512 + c);
    }
#pragma unroll
    for (int p = 0; p < 8; p++) {
        int idx = tid + p * 256; int r = idx >> 4, c = (idx & 15) * 8;
        cpasync16(Vs + r * FVS + c, Vp + (size_t)r * 1024 + c);
    }
    cpcommit();

    cpwait1();
    __syncthreads();
    uint32_t qfr[4][4];
#pragma unroll
    for (int kg = 0; kg < 4; kg++)
        ldsm_x4(qfr[kg][0], qfr[kg][1], qfr[kg][2], qfr[kg][3],
                Qs + (w16 + l16) * FQS + kg * 16 + lhi);

    float oacc[16][4];
#pragma unroll
    for (int n = 0; n < 16; n++)
#pragma unroll
        for (int r = 0; r < 4; r++) oacc[n][r] = 0.f;
    float m0 = -1e30f, m1 = -1e30f, l0 = 0.f, l1 = 0.f;

    int cur = 0;
    for (int st = 0; st < 8; st++) {
        cpwait0();
        __syncthreads();
        if (st < 7) {
            int nb = cur ^ 1;
            int s1 = (st + 1) * 128;
#pragma unroll
            for (int p = 0; p < 4; p++) {
                int idx = tid + p * 256; int r = idx >> 3, c = (idx & 7) * 8;
                cpasync16(Ks + nb * 128 * FQS + r * FQS + c, Kp + (size_t)(s1 + r) * 512 + c);
            }
#pragma unroll
            for (int p = 0; p < 8; p++) {
                int idx = tid + p * 256; int r = idx >> 4, c = (idx & 15) * 8;
                cpasync16(Vs + nb * 128 * FVS + r * FVS + c, Vp + (size_t)r * 1024 + s1 + c);
            }
            cpcommit();
        }

        // ---- S = Q·K^T : M=16 (warp rows), N=128, K=64 ----
        float sacc[16][4];
#pragma unroll
        for (int j = 0; j < 16; j++)
#pragma unroll
            for (int r = 0; r < 4; r++) sacc[j][r] = 0.f;

        const bf16* Kc = Ks + cur * 128 * FQS;
#pragma unroll
        for (int kg = 0; kg < 4; kg++) {
#pragma unroll
            for (int jp = 0; jp < 8; jp++) {
                uint32_t b0, b1, b2, b3;
                ldsm_x4(b0, b1, b2, b3, Kc + (jp * 16 + l16) * FQS + kg * 16 + lhi);
                uint32_t bfA[2] = {b0, b2}, bfB[2] = {b1, b3};
                mma16816(sacc[2 * jp],     qfr[kg], bfA);
                mma16816(sacc[2 * jp + 1], qfr[kg], bfB);
            }
        }

        // mask (raw==0) + scale 1/8
#pragma unroll
        for (int j = 0; j < 16; j++)
#pragma unroll
            for (int r = 0; r < 4; r++) {
                float v = sacc[j][r];
                sacc[j][r] = (v == 0.f) ? -1e9f : v * 0.125f;
            }

        // ---- row max (quad shuffle only) ----
        float mx0 = -1e30f, mx1 = -1e30f;
#pragma unroll
        for (int j = 0; j < 16; j++) {
            mx0 = fmaxf(mx0, fmaxf(sacc[j][0], sacc[j][1]));
            mx1 = fmaxf(mx1, fmaxf(sacc[j][2], sacc[j][3]));
        }
        mx0 = fmaxf(mx0, __shfl_xor_sync(0xffffffffu, mx0, 1));
        mx0 = fmaxf(mx0, __shfl_xor_sync(0xffffffffu, mx0, 2));
        mx1 = fmaxf(mx1, __shfl_xor_sync(0xffffffffu, mx1, 1));
        mx1 = fmaxf(mx1, __shfl_xor_sync(0xffffffffu, mx1, 2));

        float nm0 = fmaxf(m0, mx0), nm1 = fmaxf(m1, mx1);
        float scf0 = __expf(m0 - nm0), scf1 = __expf(m1 - nm1);
        m0 = nm0; m1 = nm1;

#pragma unroll
        for (int n = 0; n < 16; n++) {
            oacc[n][0] *= scf0; oacc[n][1] *= scf0;
            oacc[n][2] *= scf1; oacc[n][3] *= scf1;
        }

        // ---- P = exp(S-m) in registers + rowsum ----
        uint32_t pf[8][4];
        float rs0 = 0.f, rs1 = 0.f;
#pragma unroll
        for (int kg = 0; kg < 8; kg++) {
            int j0 = 2 * kg, j1 = 2 * kg + 1;
            float e00 = __expf(sacc[j0][0] - m0), e01 = __expf(sacc[j0][1] - m0);
            float e02 = __expf(sacc[j0][2] - m1), e03 = __expf(sacc[j0][3] - m1);
            float e10 = __expf(sacc[j1][0] - m0), e11 = __expf(sacc[j1][1] - m0);
            float e12 = __expf(sacc[j1][2] - m1), e13 = __expf(sacc[j1][3] - m1);
            rs0 += e00 + e01 + e10 + e11;
            rs1 += e02 + e03 + e12 + e13;
            pf[kg][0] = pack_bf16(e00, e01);
            pf[kg][1] = pack_bf16(e02, e03);
            pf[kg][2] = pack_bf16(e10, e11);
            pf[kg][3] = pack_bf16(e12, e13);
        }
        rs0 += __shfl_xor_sync(0xffffffffu, rs0, 1);
        rs0 += __shfl_xor_sync(0xffffffffu, rs0, 2);
        rs1 += __shfl_xor_sync(0xffffffffu, rs1, 1);
        rs1 += __shfl_xor_sync(0xffffffffu, rs1, 2);
        l0 = l0 * scf0 + rs0;
        l1 = l1 * scf1 + rs1;

        // ---- O += P·V : M=16, N=128 (d), K=128 (s) ----
        const bf16* Vc = Vs + cur * 128 * FVS;
#pragma unroll
        for (int kg = 0; kg < 8; kg++) {
#pragma unroll
            for (int np = 0; np < 8; np++) {
                uint32_t b0, b1, b2, b3;
                ldsm_x4(b0, b1, b2, b3, Vc + (np * 16 + l16) * FVS + kg * 16 + lhi);
                uint32_t bfA[2] = {b0, b2}, bfB[2] = {b1, b3};
                mma16816(oacc[2 * np],     pf[kg], bfA);
                mma16816(oacc[2 * np + 1], pf[kg], bfB);
            }
        }
        cur ^= 1;
    }

    // ---- epilogue: O / l -> ob (bf16) ----
    float inv0 = 1.f / l0, inv1 = 1.f / l1;
    int row = b * 1024 + qt * 128 + w16 + rq;
    int colb = h * 512 + dch * 128 + cq2;
#pragma unroll
    for (int n = 0; n < 16; n++) {
        int col = colb + n * 8;
        *reinterpret_cast<uint32_t*>(Og + (size_t)row * 4096 + col) =
            pack_bf16(oacc[n][0] * inv0, oacc[n][1] * inv0);
        *reinterpret_cast<uint32_t*>(Og + (size_t)(row + 8) * 4096 + col) =
            pack_bf16(oacc[n][2] * inv1, oacc[n][3] * inv1);
    }
}

// -------- LayerNorm over D=512, eps=1e-6 --------
__global__ void layernorm_k(const float* __restrict__ y, const float* __restrict__ gamma,
                            const float* __restrict__ beta, float* __restrict__ out) {
    int row = blockIdx.x;
    int t = threadIdx.x;
    const float4* p = reinterpret_cast<const float4*>(y + (size_t)row * 512);
    float4 v = p[t];
    float s = v.x + v.y + v.z + v.w;
#pragma unroll
    for (int o = 16; o; o >>= 1) s += __shfl_xor_sync(0xffffffffu, s, o);
    __shared__ float sm[4];
    if ((t & 31) == 0) sm[t >> 5] = s;
    __syncthreads();
    float mu = (sm[0] + sm[1] + sm[2] + sm[3]) * (1.0f / 512.0f);
    float dx = v.x - mu, dy = v.y - mu, dz = v.z - mu, dw = v.w - mu;
    float q = dx * dx + dy * dy + dz * dz + dw * dw;
#pragma unroll
    for (int o = 16; o; o >>= 1) q += __shfl_xor_sync(0xffffffffu, q, o);
    __shared__ float sq[4];
    if ((t & 31) == 0) sq[t >> 5] = q;
    __syncthreads();
    float var = (sq[0] + sq[1] + sq[2] + sq[3]) * (1.0f / 512.0f);
    float rs = rsqrtf(var + 1e-6f);
    float4 g = reinterpret_cast<const float4*>(gamma)[t];
    float4 b = reinterpret_cast<const float4*>(beta)[t];
    float4 r;
    r.x = dx * rs * g.x + b.x;
    r.y = dy * rs * g.y + b.y;
    r.z = dz * rs * g.z + b.z;
    r.w = dw * rs * g.w + b.w;
    reinterpret_cast<float4*>(out + (size_t)row * 512)[t] = r;
}

// ---------------------------------------------------------------
extern "C" void kernel_launch(void* const* d_in, const int* in_sizes, int n_in,
                              void* d_out, int out_size) {
    const float* x     = (const float*)d_in[0];
    const float* Wq    = (const float*)d_in[1];
    const float* Wk    = (const float*)d_in[2];
    const float* Wv    = (const float*)d_in[3];
    const float* Wo    = (const float*)d_in[4];
    const float* bo    = (const float*)d_in[5];
    const float* gamma = (const float*)d_in[6];
    const float* beta  = (const float*)d_in[7];
    float* out = (float*)d_out;

    bf16 *xb, *qb, *kb, *wqt, *wkt, *wvt, *wot, *vt, *ob;
    float *yb;
    cudaGetSymbolAddress((void**)&xb,  g_xb);
    cudaGetSymbolAddress((void**)&qb,  g_qb);
    cudaGetSymbolAddress((void**)&kb,  g_kb);
    cudaGetSymbolAddress((void**)&wqt, g_wqt);
    cudaGetSymbolAddress((void**)&wkt, g_wkt);
    cudaGetSymbolAddress((void**)&wvt, g_wvt);
    cudaGetSymbolAddress((void**)&wot, g_wot);
    cudaGetSymbolAddress((void**)&vt,  g_vt);
    cudaGetSymbolAddress((void**)&ob,  g_ob);
    cudaGetSymbolAddress((void**)&yb,  g_y);

    cudaFuncSetAttribute(flash_attn_k, cudaFuncAttributeMaxDynamicSharedMemorySize, FLASH_SMEM);

    // 1) x -> bf16
    f32_to_bf16_k<<<(int)(SZ_X / 4 / 256), 256>>>(x, xb, (int)SZ_X);
    // 2) transposed bf16 weights
    transpose_to_bf16<<<dim3(16, 16),  dim3(32, 8)>>>(Wq, wqt, 512, 512);
    transpose_to_bf16<<<dim3(16, 16),  dim3(32, 8)>>>(Wk, wkt, 512, 512);
    transpose_to_bf16<<<dim3(128, 16), dim3(32, 8)>>>(Wv, wvt, 512, 4096);
    transpose_to_bf16<<<dim3(16, 128), dim3(32, 8)>>>(Wo, wot, 4096, 512);

    // 3) q = x @ Wq   [8192,512]
    gemm_bf16_tn<1><<<dim3(4, 64, 1), 256>>>(xb, wqt, qb, 8192, 512, 512,
        512, 512, 512, 0, 0, 0, 0, 0, 0, 1, 1.0f, nullptr, nullptr, 0);
    // 4) k = x @ Wk
    gemm_bf16_tn<1><<<dim3(4, 64, 1), 256>>>(xb, wkt, kb, 8192, 512, 512,
        512, 512, 512, 0, 0, 0, 0, 0, 0, 1, 1.0f, nullptr, nullptr, 0);
    // 5) Vt[b] = WvT @ x[b]^T  -> [b][4096][1024]
    gemm_bf16_tn<1><<<dim3(8, 32, 8), 256>>>(wvt, xb, vt, 4096, 1024, 512,
        512, 512, 1024, 0, 0, 0, 524288LL, 0, 4194304LL, 1, 1.0f, nullptr, nullptr, 0);
    // 6) fused attention: scores + mask + softmax + P·V -> ob
    flash_attn_k<<<dim3(32, 64), 256, FLASH_SMEM>>>(qb, kb, vt, ob);
    // 7) y = o @ Wo + bo + x
    gemm_bf16_tn<2><<<dim3(4, 64, 1), 256>>>(ob, wot, yb, 8192, 512, 4096,
        4096, 4096, 512, 0, 0, 0, 0, 0, 0, 1, 1.0f, bo, x, 512);
    // 8) LayerNorm -> out
    layernorm_k<<<8192, 128>>>(yb, gamma, beta, out);
}

// round 9
// speedup vs baseline: 1.2430x; 1.0834x over previous
#include <cuda_runtime.h>
#include <cuda_bf16.h>
#include <cstdint>

using bf16 = __nv_bfloat16;

// Problem dims
static constexpr int NB = 8, NS = 1024, ND = 512, NK = 64, NH = 8;

static constexpr size_t SZ_X  = (size_t)NB * NS * ND;          // 4,194,304
static constexpr size_t SZ_VT = (size_t)NB * (ND * NH) * NS;   // 33,554,432
static constexpr size_t SZ_O  = (size_t)NB * NS * (NH * ND);   // 33,554,432

// -------- static scratch (no runtime allocation allowed) --------
__device__ bf16  g_xb [SZ_X];
__device__ bf16  g_qb [SZ_X];
__device__ bf16  g_kb [SZ_X];
__device__ bf16  g_wqt[ND * (NK * NH)];   // [512][512]  WqT
__device__ bf16  g_wkt[ND * (NK * NH)];   // [512][512]  WkT
__device__ bf16  g_wvt[(ND * NH) * ND];   // [4096][512] WvT
__device__ bf16  g_wot[ND * (ND * NH)];   // [512][4096] WoT
__device__ bf16  g_vt [SZ_VT];            // [b][4096][1024]  V^T per batch
__device__ bf16  g_ob [SZ_O];             // [8192][4096] attention output
__device__ float g_y  [SZ_X];             // pre-LN (o@Wo + bo + x)

// ---------------------------------------------------------------
__device__ __forceinline__ uint32_t pack_bf16(float lo, float hi) {
    return ((uint32_t)__bfloat16_as_ushort(__float2bfloat16(hi)) << 16) |
            (uint32_t)__bfloat16_as_ushort(__float2bfloat16(lo));
}

__device__ __forceinline__ void mma16816(float* d, const uint32_t* a, const uint32_t* b) {
    asm volatile(
        "mma.sync.aligned.m16n8k16.row.col.f32.bf16.bf16.f32 "
        "{%0,%1,%2,%3}, {%4,%5,%6,%7}, {%8,%9}, {%0,%1,%2,%3};\n"
        : "+f"(d[0]), "+f"(d[1]), "+f"(d[2]), "+f"(d[3])
        : "r"(a[0]), "r"(a[1]), "r"(a[2]), "r"(a[3]), "r"(b[0]), "r"(b[1]));
}

// ldmatrix x4: loads 4 8x8 bf16 matrices; per-lane row address in shared.
__device__ __forceinline__ void ldsm_x4(uint32_t& r0, uint32_t& r1, uint32_t& r2, uint32_t& r3,
                                        const void* p) {
    uint32_t a = (uint32_t)__cvta_generic_to_shared(p);
    asm volatile("ldmatrix.sync.aligned.m8n8.x4.shared.b16 {%0,%1,%2,%3}, [%4];"
                 : "=r"(r0), "=r"(r1), "=r"(r2), "=r"(r3) : "r"(a));
}

__device__ __forceinline__ void cpasync16(void* s, const void* g) {
    uint32_t sa = (uint32_t)__cvta_generic_to_shared(s);
    asm volatile("cp.async.cg.shared.global [%0], [%1], 16;\n" :: "r"(sa), "l"(g));
}
__device__ __forceinline__ void cpcommit() { asm volatile("cp.async.commit_group;\n" ::: "memory"); }
__device__ __forceinline__ void cpwait0()  { asm volatile("cp.async.wait_group 0;\n" ::: "memory"); }
__device__ __forceinline__ void cpwait1()  { asm volatile("cp.async.wait_group 1;\n" ::: "memory"); }

// -------- elementwise convert fp32 -> bf16 --------
__global__ void f32_to_bf16_k(const float* __restrict__ in, bf16* __restrict__ out, int n) {
    int i = (blockIdx.x * blockDim.x + threadIdx.x) * 4;
    if (i >= n) return;
    float4 v = *reinterpret_cast<const float4*>(in + i);
    uint2 u;
    u.x = pack_bf16(v.x, v.y);
    u.y = pack_bf16(v.z, v.w);
    *reinterpret_cast<uint2*>(out + i) = u;
}

// -------- transpose + convert: out[c][r] = in[r][c] --------
__global__ void transpose_to_bf16(const float* __restrict__ in, bf16* __restrict__ out,
                                  int R, int C) {
    __shared__ float t[32][33];
    int c0 = blockIdx.x * 32, r0 = blockIdx.y * 32;
    int tx = threadIdx.x;
    for (int i = threadIdx.y; i < 32; i += 8)
        t[i][tx] = in[(size_t)(r0 + i) * C + c0 + tx];
    __syncthreads();
    for (int i = threadIdx.y; i < 32; i += 8)
        out[(size_t)(c0 + i) * R + r0 + tx] = __float2bfloat16(t[tx][i]);
}

// -------- generic batched bf16 GEMM (cp.async double-buffered, ldmatrix frags) --------
// C[m,n] = alpha * sum_k A[m,k] * B[n,k]
// MODE 1: bf16 store     MODE 2: fp32 store + bias[n] + resid[m,n]
#define BM 128
#define BN 128
#define BK 32
#define BKP 40   // padded smem row (bf16); 80B row stride -> ldmatrix conflict-free

template <int MODE>
__global__ __launch_bounds__(256, 2)
void gemm_bf16_tn(const bf16* __restrict__ A, const bf16* __restrict__ B,
                  void* __restrict__ Cv,
                  int M, int N, int Kd, int lda, int ldb, int ldc,
                  long long sA1, long long sA2, long long sB1, long long sB2,
                  long long sC1, long long sC2, int Z1,
                  float alpha, const float* __restrict__ bias,
                  const float* __restrict__ resid, int ldres) {
    int z = blockIdx.z;
    int z1 = z % Z1, z2 = z / Z1;
    A += (size_t)z1 * sA1 + (size_t)z2 * sA2;
    B += (size_t)z1 * sB1 + (size_t)z2 * sB2;
    long long coff = (long long)z1 * sC1 + (long long)z2 * sC2;

    __shared__ alignas(16) bf16 As[2][BM][BKP];
    __shared__ alignas(16) bf16 Bs[2][BN][BKP];

    int tid  = threadIdx.x;
    int warp = tid >> 5, lane = tid & 31;
    int wm = (warp & 1) * 64;
    int wn = (warp >> 1) * 32;
    int bm0 = blockIdx.y * BM;
    int bn0 = blockIdx.x * BN;

    float acc[4][4][4];
#pragma unroll
    for (int i = 0; i < 4; i++)
#pragma unroll
        for (int j = 0; j < 4; j++)
#pragma unroll
            for (int r = 0; r < 4; r++) acc[i][j][r] = 0.f;

    int lr = tid >> 2;
    int lc = (tid & 3) * 8;
    int rq = lane >> 2;
    int cq = lane & 3;
    int l16 = lane & 15, lhi = (lane >> 4) * 8;   // ldmatrix row-in-tile / k-half

#pragma unroll
    for (int i = 0; i < 2; i++) {
        int r = lr + i * 64;
        cpasync16(&As[0][r][lc], A + (size_t)(bm0 + r) * lda + lc);
        cpasync16(&Bs[0][r][lc], B + (size_t)(bn0 + r) * ldb + lc);
    }
    cpcommit();

    int p = 0;
    for (int kt = 0; kt < Kd; kt += BK, p ^= 1) {
        cpwait0();
        __syncthreads();
        if (kt + BK < Kd) {
            int np = p ^ 1;
#pragma unroll
            for (int i = 0; i < 2; i++) {
                int r = lr + i * 64;
                cpasync16(&As[np][r][lc], A + (size_t)(bm0 + r) * lda + kt + BK + lc);
                cpasync16(&Bs[np][r][lc], B + (size_t)(bn0 + r) * ldb + kt + BK + lc);
            }
            cpcommit();
        }

#pragma unroll
        for (int ks = 0; ks < 2; ks++) {
            int kk = ks * 16 + lhi;   // bf16 element offset within row
            uint32_t afr[4][4];
#pragma unroll
            for (int i = 0; i < 4; i++)
                ldsm_x4(afr[i][0], afr[i][1], afr[i][2], afr[i][3],
                        &As[p][wm + i * 16 + l16][kk]);
            uint32_t bfr[4][2];
#pragma unroll
            for (int jp = 0; jp < 2; jp++) {
                uint32_t b0, b1, b2, b3;
                ldsm_x4(b0, b1, b2, b3, &Bs[p][wn + jp * 16 + l16][kk]);
                bfr[2 * jp][0] = b0; bfr[2 * jp][1] = b2;
                bfr[2 * jp + 1][0] = b1; bfr[2 * jp + 1][1] = b3;
            }
#pragma unroll
            for (int i = 0; i < 4; i++)
#pragma unroll
                for (int j = 0; j < 4; j++)
                    mma16816(acc[i][j], afr[i], bfr[j]);
        }
        __syncthreads();
    }

    int cq2 = cq * 2;
    float* Cf = (MODE == 1) ? nullptr : (float*)Cv + coff;
    bf16*  Cb = (MODE == 1) ? (bf16*)Cv + coff : nullptr;
#pragma unroll
    for (int i = 0; i < 4; i++) {
#pragma unroll
        for (int j = 0; j < 4; j++) {
            int row = bm0 + wm + i * 16 + rq;
            int col = bn0 + wn + j * 8 + cq2;
            float c0 = acc[i][j][0] * alpha, c1 = acc[i][j][1] * alpha;
            float c2 = acc[i][j][2] * alpha, c3 = acc[i][j][3] * alpha;
            if (MODE == 2) {
                float b0v = bias[col], b1v = bias[col + 1];
                const float* r0p = resid + (size_t)row * ldres + col;
                const float* r1p = resid + (size_t)(row + 8) * ldres + col;
                c0 += b0v + r0p[0]; c1 += b1v + r0p[1];
                c2 += b0v + r1p[0]; c3 += b1v + r1p[1];
            }
            if (MODE == 1) {
                *reinterpret_cast<uint32_t*>(Cb + (size_t)row * ldc + col)       = pack_bf16(c0, c1);
                *reinterpret_cast<uint32_t*>(Cb + (size_t)(row + 8) * ldc + col) = pack_bf16(c2, c3);
            } else {
                *reinterpret_cast<float2*>(Cf + (size_t)row * ldc + col)       = make_float2(c0, c1);
                *reinterpret_cast<float2*>(Cf + (size_t)(row + 8) * ldc + col) = make_float2(c2, c3);
            }
        }
    }
}

// ================================================================
// Fused flash attention, FA2-style warp layout + ldmatrix fragment
// loads. d-chunk = 256 (S computed 2x instead of 4x; softmax cost
// halved per unit of output). Each warp owns 16 complete query
// rows; softmax quad-shuffle-only; P stays in registers.
// Block: q-tile 128 x d-chunk 256 for one (b,h); 8 s-iters of 128.
// grid = (16, 64): x = dch*8 + qt (dch 0..1), y = b*8 + h.
// Smem: Q[128*72] | K[2][128*72] | V[2][256*136]   (~190 KB)
// ================================================================
static constexpr int FQS = 72;    // Q/K row stride bf16 (144B, 16B-aligned, conflict-free)
static constexpr int FVS = 136;   // V row stride bf16 (272B, 16B-aligned, conflict-free)
static constexpr int FLASH_SMEM = (128 * FQS * 3 + 2 * 256 * FVS) * 2;

__global__ __launch_bounds__(256, 1)
void flash_attn_k(const bf16* __restrict__ Qg, const bf16* __restrict__ Kg,
                  const bf16* __restrict__ Vg, bf16* __restrict__ Og) {
    extern __shared__ __align__(16) char fsm[];
    bf16* Qs = (bf16*)fsm;           // 128*72
    bf16* Ks = Qs + 128 * FQS;       // 2 bufs of 128*72
    bf16* Vs = Ks + 2 * 128 * FQS;   // 2 bufs of 256*136

    int tid  = threadIdx.x;
    int warp = tid >> 5, lane = tid & 31;
    int rq = lane >> 2, cq = lane & 3, cq2 = cq << 1;
    int l16 = lane & 15, lhi = (lane >> 4) * 8;
    int w16 = warp * 16;
    int qt = blockIdx.x & 7, dch = blockIdx.x >> 3;   // dch 0..1
    int b  = blockIdx.y >> 3, h = blockIdx.y & 7;

    const bf16* Qp = Qg + ((size_t)(b * 1024 + qt * 128)) * 512 + h * 64;
    const bf16* Kp = Kg + ((size_t)(b * 1024)) * 512 + h * 64;
    const bf16* Vp = Vg + (size_t)b * 4194304 + ((size_t)(h * 512 + dch * 256)) * 1024;

#pragma unroll
    for (int p = 0; p < 4; p++) {
        int idx = tid + p * 256; int r = idx >> 3, c = (idx & 7) * 8;
        cpasync16(Qs + r * FQS + c, Qp + (size_t)r * 512 + c);
    }
    cpcommit();
#pragma unroll
    for (int p = 0; p < 4; p++) {
        int idx = tid + p * 256; int r = idx >> 3, c = (idx & 7) * 8;
        cpasync16(Ks + r * FQS + c, Kp + (size_t)r * 512 + c);
    }
#pragma unroll
    for (int p = 0; p < 16; p++) {
        int idx = tid + p * 256; int r = idx >> 4, c = (idx & 15) * 8;
        cpasync16(Vs + r * FVS + c, Vp + (size_t)r * 1024 + c);
    }
    cpcommit();

    cpwait1();
    __syncthreads();
    uint32_t qfr[4][4];
#pragma unroll
    for (int kg = 0; kg < 4; kg++)
        ldsm_x4(qfr[kg][0], qfr[kg][1], qfr[kg][2], qfr[kg][3],
                Qs + (w16 + l16) * FQS + kg * 16 + lhi);

    float oacc[32][4];
#pragma unroll
    for (int n = 0; n < 32; n++)
#pragma unroll
        for (int r = 0; r < 4; r++) oacc[n][r] = 0.f;
    float m0 = -1e30f, m1 = -1e30f, l0 = 0.f, l1 = 0.f;

    int cur = 0;
    for (int st = 0; st < 8; st++) {
        cpwait0();
        __syncthreads();
        if (st < 7) {
            int nb = cur ^ 1;
            int s1 = (st + 1) * 128;
#pragma unroll
            for (int p = 0; p < 4; p++) {
                int idx = tid + p * 256; int r = idx >> 3, c = (idx & 7) * 8;
                cpasync16(Ks + nb * 128 * FQS + r * FQS + c, Kp + (size_t)(s1 + r) * 512 + c);
            }
#pragma unroll
            for (int p = 0; p < 16; p++) {
                int idx = tid + p * 256; int r = idx >> 4, c = (idx & 15) * 8;
                cpasync16(Vs + nb * 256 * FVS + r * FVS + c, Vp + (size_t)r * 1024 + s1 + c);
            }
            cpcommit();
        }

        // ---- S = Q·K^T : M=16 (warp rows), N=128, K=64 ----
        float sacc[16][4];
#pragma unroll
        for (int j = 0; j < 16; j++)
#pragma unroll
            for (int r = 0; r < 4; r++) sacc[j][r] = 0.f;

        const bf16* Kc = Ks + cur * 128 * FQS;
#pragma unroll
        for (int kg = 0; kg < 4; kg++) {
#pragma unroll
            for (int jp = 0; jp < 8; jp++) {
                uint32_t b0, b1, b2, b3;
                ldsm_x4(b0, b1, b2, b3, Kc + (jp * 16 + l16) * FQS + kg * 16 + lhi);
                uint32_t bfA[2] = {b0, b2}, bfB[2] = {b1, b3};
                mma16816(sacc[2 * jp],     qfr[kg], bfA);
                mma16816(sacc[2 * jp + 1], qfr[kg], bfB);
            }
        }

        // mask (raw==0) + scale 1/8
#pragma unroll
        for (int j = 0; j < 16; j++)
#pragma unroll
            for (int r = 0; r < 4; r++) {
                float v = sacc[j][r];
                sacc[j][r] = (v == 0.f) ? -1e9f : v * 0.125f;
            }

        // ---- row max (quad shuffle only) ----
        float mx0 = -1e30f, mx1 = -1e30f;
#pragma unroll
        for (int j = 0; j < 16; j++) {
            mx0 = fmaxf(mx0, fmaxf(sacc[j][0], sacc[j][1]));
            mx1 = fmaxf(mx1, fmaxf(sacc[j][2], sacc[j][3]));
        }
        mx0 = fmaxf(mx0, __shfl_xor_sync(0xffffffffu, mx0, 1));
        mx0 = fmaxf(mx0, __shfl_xor_sync(0xffffffffu, mx0, 2));
        mx1 = fmaxf(mx1, __shfl_xor_sync(0xffffffffu, mx1, 1));
        mx1 = fmaxf(mx1, __shfl_xor_sync(0xffffffffu, mx1, 2));

        float nm0 = fmaxf(m0, mx0), nm1 = fmaxf(m1, mx1);
        float scf0 = __expf(m0 - nm0), scf1 = __expf(m1 - nm1);
        m0 = nm0; m1 = nm1;

#pragma unroll
        for (int n = 0; n < 32; n++) {
            oacc[n][0] *= scf0; oacc[n][1] *= scf0;
            oacc[n][2] *= scf1; oacc[n][3] *= scf1;
        }

        // ---- P = exp(S-m) in registers + rowsum ----
        uint32_t pf[8][4];
        float rs0 = 0.f, rs1 = 0.f;
#pragma unroll
        for (int kg = 0; kg < 8; kg++) {
            int j0 = 2 * kg, j1 = 2 * kg + 1;
            float e00 = __expf(sacc[j0][0] - m0), e01 = __expf(sacc[j0][1] - m0);
            float e02 = __expf(sacc[j0][2] - m1), e03 = __expf(sacc[j0][3] - m1);
            float e10 = __expf(sacc[j1][0] - m0), e11 = __expf(sacc[j1][1] - m0);
            float e12 = __expf(sacc[j1][2] - m1), e13 = __expf(sacc[j1][3] - m1);
            rs0 += e00 + e01 + e10 + e11;
            rs1 += e02 + e03 + e12 + e13;
            pf[kg][0] = pack_bf16(e00, e01);
            pf[kg][1] = pack_bf16(e02, e03);
            pf[kg][2] = pack_bf16(e10, e11);
            pf[kg][3] = pack_bf16(e12, e13);
        }
        rs0 += __shfl_xor_sync(0xffffffffu, rs0, 1);
        rs0 += __shfl_xor_sync(0xffffffffu, rs0, 2);
        rs1 += __shfl_xor_sync(0xffffffffu, rs1, 1);
        rs1 += __shfl_xor_sync(0xffffffffu, rs1, 2);
        l0 = l0 * scf0 + rs0;
        l1 = l1 * scf1 + rs1;

        // ---- O += P·V : M=16, N=256 (d), K=128 (s) ----
        const bf16* Vc = Vs + cur * 256 * FVS;
#pragma unroll
        for (int kg = 0; kg < 8; kg++) {
#pragma unroll
            for (int np = 0; np < 16; np++) {
                uint32_t b0, b1, b2, b3;
                ldsm_x4(b0, b1, b2, b3, Vc + (np * 16 + l16) * FVS + kg * 16 + lhi);
                uint32_t bfA[2] = {b0, b2}, bfB[2] = {b1, b3};
                mma16816(oacc[2 * np],     pf[kg], bfA);
                mma16816(oacc[2 * np + 1], pf[kg], bfB);
            }
        }
        cur ^= 1;
    }

    // ---- epilogue: O / l -> ob (bf16) ----
    float inv0 = 1.f / l0, inv1 = 1.f / l1;
    int row = b * 1024 + qt * 128 + w16 + rq;
    int colb = h * 512 + dch * 256 + cq2;
#pragma unroll
    for (int n = 0; n < 32; n++) {
        int col = colb + n * 8;
        *reinterpret_cast<uint32_t*>(Og + (size_t)row * 4096 + col) =
            pack_bf16(oacc[n][0] * inv0, oacc[n][1] * inv0);
        *reinterpret_cast<uint32_t*>(Og + (size_t)(row + 8) * 4096 + col) =
            pack_bf16(oacc[n][2] * inv1, oacc[n][3] * inv1);
    }
}

// -------- LayerNorm over D=512, eps=1e-6 --------
__global__ void layernorm_k(const float* __restrict__ y, const float* __restrict__ gamma,
                            const float* __restrict__ beta, float* __restrict__ out) {
    int row = blockIdx.x;
    int t = threadIdx.x;
    const float4* p = reinterpret_cast<const float4*>(y + (size_t)row * 512);
    float4 v = p[t];
    float s = v.x + v.y + v.z + v.w;
#pragma unroll
    for (int o = 16; o; o >>= 1) s += __shfl_xor_sync(0xffffffffu, s, o);
    __shared__ float sm[4];
    if ((t & 31) == 0) sm[t >> 5] = s;
    __syncthreads();
    float mu = (sm[0] + sm[1] + sm[2] + sm[3]) * (1.0f / 512.0f);
    float dx = v.x - mu, dy = v.y - mu, dz = v.z - mu, dw = v.w - mu;
    float q = dx * dx + dy * dy + dz * dz + dw * dw;
#pragma unroll
    for (int o = 16; o; o >>= 1) q += __shfl_xor_sync(0xffffffffu, q, o);
    __shared__ float sq[4];
    if ((t & 31) == 0) sq[t >> 5] = q;
    __syncthreads();
    float var = (sq[0] + sq[1] + sq[2] + sq[3]) * (1.0f / 512.0f);
    float rs = rsqrtf(var + 1e-6f);
    float4 g = reinterpret_cast<const float4*>(gamma)[t];
    float4 b = reinterpret_cast<const float4*>(beta)[t];
    float4 r;
    r.x = dx * rs * g.x + b.x;
    r.y = dy * rs * g.y + b.y;
    r.z = dz * rs * g.z + b.z;
    r.w = dw * rs * g.w + b.w;
    reinterpret_cast<float4*>(out + (size_t)row * 512)[t] = r;
}

// ---------------------------------------------------------------
extern "C" void kernel_launch(void* const* d_in, const int* in_sizes, int n_in,
                              void* d_out, int out_size) {
    const float* x     = (const float*)d_in[0];
    const float* Wq    = (const float*)d_in[1];
    const float* Wk    = (const float*)d_in[2];
    const float* Wv    = (const float*)d_in[3];
    const float* Wo    = (const float*)d_in[4];
    const float* bo    = (const float*)d_in[5];
    const float* gamma = (const float*)d_in[6];
    const float* beta  = (const float*)d_in[7];
    float* out = (float*)d_out;

    bf16 *xb, *qb, *kb, *wqt, *wkt, *wvt, *wot, *vt, *ob;
    float *yb;
    cudaGetSymbolAddress((void**)&xb,  g_xb);
    cudaGetSymbolAddress((void**)&qb,  g_qb);
    cudaGetSymbolAddress((void**)&kb,  g_kb);
    cudaGetSymbolAddress((void**)&wqt, g_wqt);
    cudaGetSymbolAddress((void**)&wkt, g_wkt);
    cudaGetSymbolAddress((void**)&wvt, g_wvt);
    cudaGetSymbolAddress((void**)&wot, g_wot);
    cudaGetSymbolAddress((void**)&vt,  g_vt);
    cudaGetSymbolAddress((void**)&ob,  g_ob);
    cudaGetSymbolAddress((void**)&yb,  g_y);

    cudaFuncSetAttribute(flash_attn_k, cudaFuncAttributeMaxDynamicSharedMemorySize, FLASH_SMEM);

    // 1) x -> bf16
    f32_to_bf16_k<<<(int)(SZ_X / 4 / 256), 256>>>(x, xb, (int)SZ_X);
    // 2) transposed bf16 weights
    transpose_to_bf16<<<dim3(16, 16),  dim3(32, 8)>>>(Wq, wqt, 512, 512);
    transpose_to_bf16<<<dim3(16, 16),  dim3(32, 8)>>>(Wk, wkt, 512, 512);
    transpose_to_bf16<<<dim3(128, 16), dim3(32, 8)>>>(Wv, wvt, 512, 4096);
    transpose_to_bf16<<<dim3(16, 128), dim3(32, 8)>>>(Wo, wot, 4096, 512);

    // 3) q = x @ Wq   [8192,512]
    gemm_bf16_tn<1><<<dim3(4, 64, 1), 256>>>(xb, wqt, qb, 8192, 512, 512,
        512, 512, 512, 0, 0, 0, 0, 0, 0, 1, 1.0f, nullptr, nullptr, 0);
    // 4) k = x @ Wk
    gemm_bf16_tn<1><<<dim3(4, 64, 1), 256>>>(xb, wkt, kb, 8192, 512, 512,
        512, 512, 512, 0, 0, 0, 0, 0, 0, 1, 1.0f, nullptr, nullptr, 0);
    // 5) Vt[b] = WvT @ x[b]^T  -> [b][4096][1024]
    gemm_bf16_tn<1><<<dim3(8, 32, 8), 256>>>(wvt, xb, vt, 4096, 1024, 512,
        512, 512, 1024, 0, 0, 0, 524288LL, 0, 4194304LL, 1, 1.0f, nullptr, nullptr, 0);
    // 6) fused attention: scores + mask + softmax + P·V -> ob  (d-chunk 256)
    flash_attn_k<<<dim3(16, 64), 256, FLASH_SMEM>>>(qb, kb, vt, ob);
    // 7) y = o @ Wo + bo + x
    gemm_bf16_tn<2><<<dim3(4, 64, 1), 256>>>(ob, wot, yb, 8192, 512, 4096,
        4096, 4096, 512, 0, 0, 0, 0, 0, 0, 1, 1.0f, bo, x, 512);
    // 8) LayerNorm -> out
    layernorm_k<<<8192, 128>>>(yb, gamma, beta, out);
}